// round 4
// baseline (speedup 1.0000x reference)
#include <cuda_runtime.h>
#include <math.h>

typedef unsigned long long ull;

#define NB    64
#define CIN   8
#define COUT  8
#define NLAT  128
#define NLON  256
#define M0D   16
#define M1D   16

// ---------------- device scratch (no allocations allowed) ----------------
__device__ float  g_wfwd[NLAT * M0D * M1D];   // [k][l][m]  (wq*2pi/256 and CS sign folded in)
__device__ float  g_pct [M1D * M0D * NLAT];   // [m][l][k]  (CS sign folded in)
__device__ float2 g_tw  [NLON * M1D];         // fwd twiddles [n][m] = (cos th, -sin th)
__device__ float2 g_itw [NLON * M1D];         // inv twiddles [n][m] = (c, s); spec += Xr*c + Xi*s
__device__ float  g_z   [NB * 4096];          // forward spectral features  [b][c*512+l*32+m*2+ri]
__device__ float  g_h   [NB * 8192];          // MLP hidden
__device__ float  g_oh  [2 * NB * 4096];      // MLP out, split-K partials

// ---------------- helpers ----------------
__device__ __forceinline__ ull pack2(float a, float b) {
    ull d;
    asm("mov.b64 %0, {%1, %2};" : "=l"(d) : "r"(__float_as_uint(a)), "r"(__float_as_uint(b)));
    return d;
}
__device__ __forceinline__ ull ffma2(ull a, ull b, ull c) {
    ull d;
    asm("fma.rn.f32x2 %0, %1, %2, %3;" : "=l"(d) : "l"(a), "l"(b), "l"(c));
    return d;
}
__device__ __forceinline__ float2 unpack2(ull v) {
    unsigned lo, hi;
    asm("mov.b64 {%0, %1}, %2;" : "=r"(lo), "=r"(hi) : "l"(v));
    float2 r; r.x = __uint_as_float(lo); r.y = __uint_as_float(hi);
    return r;
}
__device__ __forceinline__ float gelu_exact(float x) {
    return 0.5f * x * (1.0f + erff(x * 0.70710678118654752440f));
}

// ---------------- setup: CC quadrature + Legendre tables (fp64) ----------------
__global__ void k_setup_leg() {
    int j = threadIdx.x;
    if (j >= NLAT) return;
    const double PI = 3.14159265358979323846;
    const double Nd = (double)(NLAT - 1);
    double x = -cos(PI * (double)j / Nd);          // ct[j]
    double tj = PI * (double)j / Nd;               // wq symmetric -> same pairing
    double w = 2.0 / Nd;
    for (int kk = 1; kk <= (NLAT - 1) / 2; kk++)
        w -= 2.0 * cos(2.0 * (double)kk * tj) * (2.0 / Nd) / (4.0 * (double)kk * kk - 1.0);
    if (j == 0 || j == NLAT - 1) w *= 0.5;

    double vdm[M1D][M0D];
    for (int a = 0; a < M1D; a++)
        for (int b = 0; b < M0D; b++) vdm[a][b] = 0.0;
    vdm[0][0] = 1.0 / sqrt(4.0 * PI);
    for (int l = 1; l < M0D; l++) {
        vdm[l - 1][l] = sqrt(2.0 * l + 1.0) * x * vdm[l - 1][l - 1];
        vdm[l][l]     = sqrt((2.0 * l + 1.0) * (1.0 + x) * (1.0 - x) / 2.0 / (double)l) * vdm[l - 1][l - 1];
    }
    for (int l = 2; l < M0D; l++) {
        for (int m = 0; m < l - 1; m++) {
            double a = sqrt((2.0 * l - 1.0) / (l - m) * (2.0 * l + 1.0) / (l + m));
            double b = sqrt((l + m - 1.0) / (l - m) * (2.0 * l + 1.0) / (2.0 * l - 3.0) *
                            (l - m - 1.0) / (l + m));
            vdm[m][l] = a * x * vdm[m][l - 1] - b * vdm[m][l - 2];
        }
    }
    const double sc = 2.0 * PI / (double)NLON;
    for (int m = 0; m < M1D; m++) {
        double sgn = (m & 1) ? -1.0 : 1.0;
        for (int l = 0; l < M0D; l++) {
            double v = vdm[m][l] * sgn;
            g_wfwd[j * 256 + l * 16 + m]       = (float)(v * w * sc);  // [k][l][m]
            g_pct[(m * M0D + l) * NLAT + j]    = (float)v;             // [m][l][k]
        }
    }
}

__global__ void k_setup_tw() {
    int g = blockIdx.x * blockDim.x + threadIdx.x;   // 0..8191
    const double PI = 3.14159265358979323846;
    if (g < NLON * M1D) {
        int n = g >> 4, m = g & 15;
        double th = 2.0 * PI * (double)((m * n) & (NLON - 1)) / (double)NLON;
        g_tw[g] = make_float2((float)cos(th), (float)(-sin(th)));
    } else {
        int h = g - NLON * M1D;
        int n = h >> 4, m = h & 15;
        double th = 2.0 * PI * (double)((m * n) & (NLON - 1)) / (double)NLON;
        float c = (m == 0) ? 1.0f : (float)(2.0 * cos(th));
        float s = (m == 0) ? 0.0f : (float)(-2.0 * sin(th));
        g_itw[h] = make_float2(c, s);
    }
}

// ---------------- forward: 16-mode DFT + Legendre -> g_z ----------------
// one block per (b,c); 256 threads
__global__ void __launch_bounds__(256) k_forward(const float* __restrict__ x) {
    __shared__ __align__(16) float xs[32 * 65];   // x chunk [k_local][n_local], padded
    __shared__ ull tws_u[64 * 16];                // twiddle chunk [n_local][m]
    __shared__ ull Ys_u[NLAT * 16];               // DFT output [k][m] complex

    int bc  = blockIdx.x;
    int tid = threadIdx.x;
    int kg  = tid >> 4;          // 0..15 -> handles k_local = 2*kg, 2*kg+1
    int m   = tid & 15;
    const float* xb = x + (size_t)bc * NLAT * NLON;

    for (int kc = 0; kc < 4; kc++) {             // 4 chunks of 32 latitude rows
        ull acc0 = 0ull, acc1 = 0ull;
        for (int nc = 0; nc < 4; nc++) {         // 4 chunks of 64 longitude cols
            #pragma unroll
            for (int i = 0; i < 8; i++) {
                int idx = i * 256 + tid;
                int kl = idx >> 6, nn = idx & 63;
                xs[kl * 65 + nn] = xb[(kc * 32 + kl) * NLON + nc * 64 + nn];
            }
            #pragma unroll
            for (int i = 0; i < 4; i++) {
                int idx = i * 256 + tid;
                tws_u[idx] = ((const ull*)g_tw)[nc * 1024 + idx];
            }
            __syncthreads();
            #pragma unroll 4
            for (int n = 0; n < 64; n++) {
                ull tw = tws_u[n * 16 + m];
                float x0 = xs[(kg * 2) * 65 + n];
                float x1 = xs[(kg * 2 + 1) * 65 + n];
                acc0 = ffma2(pack2(x0, x0), tw, acc0);
                acc1 = ffma2(pack2(x1, x1), tw, acc1);
            }
            __syncthreads();
        }
        Ys_u[(kc * 32 + kg * 2) * 16 + m]     = acc0;
        Ys_u[(kc * 32 + kg * 2 + 1) * 16 + m] = acc1;
    }
    __syncthreads();

    // stage 2: xh[l][m] = sum_k wfwd[k][l][m] * Y[k][m]
    ull acc = 0ull;
    const float* wcol = g_wfwd + tid;   // tid = l*16+m -> [k][l][m] coalesced
    #pragma unroll 8
    for (int k = 0; k < NLAT; k++) {
        float wv = wcol[k * 256];
        acc = ffma2(pack2(wv, wv), Ys_u[k * 16 + m], acc);
    }
    float2 r = unpack2(acc);
    int b = bc >> 3, c = bc & 7;
    int l = tid >> 4;
    float2* zp = (float2*)(g_z + (size_t)b * 4096 + c * 512 + l * 32 + m * 2);
    *zp = make_float2(r.x, r.y);
}

// ---------------- GEMM: C[64 x N] = A[64 x K] @ B[N x K]^T (+bias,+gelu) ----------------
// mode 0: A=g_z (lda 4096), C=g_h, N=8192, bias+gelu. mode 1: A=g_h (lda 8192), C=g_oh splitK partials.
__global__ void __launch_bounds__(256) k_gemm(int mode,
    const float* __restrict__ B, const float* __restrict__ bias)
{
    __shared__ __align__(16) float As[32 * 68];
    __shared__ __align__(16) float Bs[32 * 68];

    const float* A; float* C; int lda, N;
    if (mode == 0) { A = g_z; C = g_h;  lda = 4096; N = 8192; }
    else           { A = g_h; C = g_oh; lda = 8192; N = 4096; }
    const int kIters = 128;
    int tid  = threadIdx.x;
    int n0   = blockIdx.x * 64;
    int kOff = blockIdx.y * (kIters * 32);
    C += (size_t)blockIdx.y * 64 * N;

    int m0 = (tid & 15) * 4;
    int n4 = (tid >> 4) * 4;
    int row = tid >> 3;
    int kq  = (tid & 7) * 4;

    ull acc[4][2];
    #pragma unroll
    for (int i = 0; i < 4; i++) { acc[i][0] = 0ull; acc[i][1] = 0ull; }

    for (int it = 0; it < kIters; it++) {
        int k0 = kOff + it * 32;
        float4 avr[2], bvr[2];
        #pragma unroll
        for (int rr = 0; rr < 2; rr++) {
            int rrow = row + rr * 32;
            avr[rr] = *(const float4*)(A + (size_t)rrow * lda + k0 + kq);
            bvr[rr] = *(const float4*)(B + (size_t)(n0 + rrow) * lda + k0 + kq);
        }
        __syncthreads();
        #pragma unroll
        for (int rr = 0; rr < 2; rr++) {
            int rrow = row + rr * 32;
            As[(kq + 0) * 68 + rrow] = avr[rr].x;
            As[(kq + 1) * 68 + rrow] = avr[rr].y;
            As[(kq + 2) * 68 + rrow] = avr[rr].z;
            As[(kq + 3) * 68 + rrow] = avr[rr].w;
            Bs[(kq + 0) * 68 + rrow] = bvr[rr].x;
            Bs[(kq + 1) * 68 + rrow] = bvr[rr].y;
            Bs[(kq + 2) * 68 + rrow] = bvr[rr].z;
            Bs[(kq + 3) * 68 + rrow] = bvr[rr].w;
        }
        __syncthreads();
        #pragma unroll 8
        for (int k = 0; k < 32; k++) {
            float4 a = *(const float4*)&As[k * 68 + m0];
            ulonglong2 bu = *(const ulonglong2*)&Bs[k * 68 + n4];
            ull a0 = pack2(a.x, a.x), a1 = pack2(a.y, a.y);
            ull a2 = pack2(a.z, a.z), a3 = pack2(a.w, a.w);
            acc[0][0] = ffma2(a0, bu.x, acc[0][0]);
            acc[0][1] = ffma2(a0, bu.y, acc[0][1]);
            acc[1][0] = ffma2(a1, bu.x, acc[1][0]);
            acc[1][1] = ffma2(a1, bu.y, acc[1][1]);
            acc[2][0] = ffma2(a2, bu.x, acc[2][0]);
            acc[2][1] = ffma2(a2, bu.y, acc[2][1]);
            acc[3][0] = ffma2(a3, bu.x, acc[3][0]);
            acc[3][1] = ffma2(a3, bu.y, acc[3][1]);
        }
    }

    float4 bsv = make_float4(0.f, 0.f, 0.f, 0.f);
    if (mode == 0) bsv = *(const float4*)(bias + n0 + n4);
    #pragma unroll
    for (int i = 0; i < 4; i++) {
        float2 v0 = unpack2(acc[i][0]);
        float2 v1 = unpack2(acc[i][1]);
        float4 o;
        o.x = v0.x; o.y = v0.y; o.z = v1.x; o.w = v1.y;
        if (mode == 0) {
            o.x = gelu_exact(o.x + bsv.x);
            o.y = gelu_exact(o.y + bsv.y);
            o.z = gelu_exact(o.z + bsv.z);
            o.w = gelu_exact(o.w + bsv.w);
        }
        *(float4*)(C + (size_t)(m0 + i) * N + n0 + n4) = o;
    }
}

// ---------------- inverse: Legendre + inverse DFT + bypass + gelu ----------------
// one block per (b, k-quarter); 256 threads
__global__ void __launch_bounds__(256) k_inverse(const float* __restrict__ x,
    const float* __restrict__ cw, const float* __restrict__ cb,
    float* __restrict__ out)
{
    __shared__ __align__(16) ull xks_u[8 * 32 * 16];   // [c][k_local][m] complex, 32KB
    __shared__ float cws[64];
    __shared__ float cbs[8];

    int tid = threadIdx.x;
    int b   = blockIdx.x >> 2;
    int kq  = blockIdx.x & 3;

    if (tid < 64) cws[tid] = cw[tid];
    if (tid < 8)  cbs[tid] = cb[tid];

    // stage 2: xk[c][k][m] = sum_l oh[c][l][m] * pct[m][l][k]
    {
        int c  = tid >> 5;
        int kl = tid & 31;
        const float* p0 = g_oh + (size_t)b * 4096 + c * 512;
        const float* p1 = g_oh + (size_t)NB * 4096 + (size_t)b * 4096 + c * 512;
        #pragma unroll 4
        for (int m = 0; m < 16; m++) {
            ull acc = 0ull;
            #pragma unroll
            for (int l = 0; l < 16; l++) {
                int off = l * 32 + m * 2;
                float orr = p0[off]     + p1[off];
                float oi  = p0[off + 1] + p1[off + 1];
                float pv  = g_pct[(m * 16 + l) * NLAT + kq * 32 + kl];
                acc = ffma2(pack2(pv, pv), pack2(orr, oi), acc);
            }
            xks_u[(c * 32 + kl) * 16 + m] = acc;
        }
    }
    __syncthreads();

    // stage 3: per longitude column n = tid
    int n = tid;
    ull itw_r[16];
    #pragma unroll
    for (int m = 0; m < 16; m++)
        itw_r[m] = ((const ull*)g_itw)[n * 16 + m];

    for (int kl = 0; kl < 32; kl++) {
        int k = kq * 32 + kl;
        float xv[8];
        #pragma unroll
        for (int c = 0; c < 8; c++)
            xv[c] = x[(((size_t)b * 8 + c) * NLAT + k) * NLON + n];
        #pragma unroll
        for (int o = 0; o < 8; o++) {
            ull acc = 0ull;
            #pragma unroll
            for (int m = 0; m < 16; m++)
                acc = ffma2(xks_u[(o * 32 + kl) * 16 + m], itw_r[m], acc);
            float2 ar = unpack2(acc);
            float spec = ar.x + ar.y;
            float byp = cbs[o];
            #pragma unroll
            for (int c = 0; c < 8; c++)
                byp = fmaf(xv[c], cws[o * 8 + c], byp);
            out[(((size_t)b * 8 + o) * NLAT + k) * NLON + n] = gelu_exact(spec + byp);
        }
    }
}

// ---------------- launch ----------------
extern "C" void kernel_launch(void* const* d_in, const int* in_sizes, int n_in,
                              void* d_out, int out_size) {
    const float* x  = (const float*)d_in[0];
    const float* w0 = (const float*)d_in[1];
    const float* b0 = (const float*)d_in[2];
    const float* w1 = (const float*)d_in[3];
    const float* cw = (const float*)d_in[4];
    const float* cb = (const float*)d_in[5];
    float* out = (float*)d_out;

    k_setup_leg<<<1, 128>>>();
    k_setup_tw<<<32, 256>>>();
    k_forward<<<NB * CIN, 256>>>(x);
    k_gemm<<<dim3(128, 1), 256>>>(0, w0, b0);      // z @ w0^T + b0, gelu -> g_h
    k_gemm<<<dim3(64, 2), 256>>>(1, w1, nullptr);  // h @ w1^T -> g_oh (splitK=2 partials)
    k_inverse<<<NB * 4, 256>>>(x, cw, cb, out);
}

// round 5
// speedup vs baseline: 1.1372x; 1.1372x over previous
#include <cuda_runtime.h>
#include <math.h>

typedef unsigned long long ull;

#define NB    64
#define CIN   8
#define COUT  8
#define NLAT  128
#define NLON  256
#define M0D   16
#define M1D   16

// ---------------- device scratch (no allocations allowed) ----------------
__device__ float  g_wfwd[NLAT * M0D * M1D];   // [k][l][m]  (wq*2pi/256 and CS sign folded in)
__device__ float  g_pct [M1D * M0D * NLAT];   // [m][l][k]  (CS sign folded in)
__device__ float2 g_tw  [NLON * M1D];         // fwd twiddles [n][m] = (cos th, -sin th)
__device__ float2 g_itw [NLON * M1D];         // inv twiddles [n][m] = (c, s); spec += Xr*c + Xi*s
__device__ float  g_z   [NB * 4096];          // forward spectral features  [b][c*512+l*32+m*2+ri]
__device__ float  g_h   [NB * 8192];          // MLP hidden (post bias+gelu)
__device__ float  g_p1  [4 * NB * 8192];      // GEMM1 split-K partials (8MB)
__device__ float  g_p2  [8 * NB * 4096];      // GEMM2 split-K partials (8MB)
__device__ float  g_ohf [NB * 4096];          // reduced MLP output

// ---------------- helpers ----------------
__device__ __forceinline__ ull pack2(float a, float b) {
    ull d;
    asm("mov.b64 %0, {%1, %2};" : "=l"(d) : "r"(__float_as_uint(a)), "r"(__float_as_uint(b)));
    return d;
}
__device__ __forceinline__ ull ffma2(ull a, ull b, ull c) {
    ull d;
    asm("fma.rn.f32x2 %0, %1, %2, %3;" : "=l"(d) : "l"(a), "l"(b), "l"(c));
    return d;
}
__device__ __forceinline__ float2 unpack2(ull v) {
    unsigned lo, hi;
    asm("mov.b64 {%0, %1}, %2;" : "=r"(lo), "=r"(hi) : "l"(v));
    float2 r; r.x = __uint_as_float(lo); r.y = __uint_as_float(hi);
    return r;
}
__device__ __forceinline__ float gelu_exact(float x) {
    return 0.5f * x * (1.0f + erff(x * 0.70710678118654752440f));
}

// ---------------- setup: CC quadrature + Legendre tables (fp64) ----------------
__global__ void k_setup_leg() {
    int j = threadIdx.x;
    if (j >= NLAT) return;
    const double PI = 3.14159265358979323846;
    const double Nd = (double)(NLAT - 1);
    double x = -cos(PI * (double)j / Nd);          // ct[j]
    double tj = PI * (double)j / Nd;
    double w = 2.0 / Nd;
    for (int kk = 1; kk <= (NLAT - 1) / 2; kk++)
        w -= 2.0 * cos(2.0 * (double)kk * tj) * (2.0 / Nd) / (4.0 * (double)kk * kk - 1.0);
    if (j == 0 || j == NLAT - 1) w *= 0.5;

    double vdm[M1D][M0D];
    for (int a = 0; a < M1D; a++)
        for (int b = 0; b < M0D; b++) vdm[a][b] = 0.0;
    vdm[0][0] = 1.0 / sqrt(4.0 * PI);
    for (int l = 1; l < M0D; l++) {
        vdm[l - 1][l] = sqrt(2.0 * l + 1.0) * x * vdm[l - 1][l - 1];
        vdm[l][l]     = sqrt((2.0 * l + 1.0) * (1.0 + x) * (1.0 - x) / 2.0 / (double)l) * vdm[l - 1][l - 1];
    }
    for (int l = 2; l < M0D; l++) {
        for (int m = 0; m < l - 1; m++) {
            double a = sqrt((2.0 * l - 1.0) / (l - m) * (2.0 * l + 1.0) / (l + m));
            double b = sqrt((l + m - 1.0) / (l - m) * (2.0 * l + 1.0) / (2.0 * l - 3.0) *
                            (l - m - 1.0) / (l + m));
            vdm[m][l] = a * x * vdm[m][l - 1] - b * vdm[m][l - 2];
        }
    }
    const double sc = 2.0 * PI / (double)NLON;
    for (int m = 0; m < M1D; m++) {
        double sgn = (m & 1) ? -1.0 : 1.0;
        for (int l = 0; l < M0D; l++) {
            double v = vdm[m][l] * sgn;
            g_wfwd[j * 256 + l * 16 + m]       = (float)(v * w * sc);  // [k][l][m]
            g_pct[(m * M0D + l) * NLAT + j]    = (float)v;             // [m][l][k]
        }
    }
}

__global__ void k_setup_tw() {
    int g = blockIdx.x * blockDim.x + threadIdx.x;   // 0..8191
    const double PI = 3.14159265358979323846;
    if (g < NLON * M1D) {
        int n = g >> 4, m = g & 15;
        double th = 2.0 * PI * (double)((m * n) & (NLON - 1)) / (double)NLON;
        g_tw[g] = make_float2((float)cos(th), (float)(-sin(th)));
    } else {
        int h = g - NLON * M1D;
        int n = h >> 4, m = h & 15;
        double th = 2.0 * PI * (double)((m * n) & (NLON - 1)) / (double)NLON;
        float c = (m == 0) ? 1.0f : (float)(2.0 * cos(th));
        float s = (m == 0) ? 0.0f : (float)(-2.0 * sin(th));
        g_itw[h] = make_float2(c, s);
    }
}

// ---------------- forward: 16-mode DFT + Legendre -> g_z ----------------
// one block per (b,c); 256 threads
__global__ void __launch_bounds__(256) k_forward(const float* __restrict__ x) {
    __shared__ __align__(16) float xs[32 * 65];   // x chunk [k_local][n_local], padded
    __shared__ ull tws_u[64 * 16];                // twiddle chunk [n_local][m]
    __shared__ ull Ys_u[NLAT * 16];               // DFT output [k][m] complex

    int bc  = blockIdx.x;
    int tid = threadIdx.x;
    int kg  = tid >> 4;          // 0..15 -> handles k_local = 2*kg, 2*kg+1
    int m   = tid & 15;
    const float* xb = x + (size_t)bc * NLAT * NLON;

    for (int kc = 0; kc < 4; kc++) {             // 4 chunks of 32 latitude rows
        ull acc0 = 0ull, acc1 = 0ull;
        for (int nc = 0; nc < 4; nc++) {         // 4 chunks of 64 longitude cols
            #pragma unroll
            for (int i = 0; i < 8; i++) {
                int idx = i * 256 + tid;
                int kl = idx >> 6, nn = idx & 63;
                xs[kl * 65 + nn] = xb[(kc * 32 + kl) * NLON + nc * 64 + nn];
            }
            #pragma unroll
            for (int i = 0; i < 4; i++) {
                int idx = i * 256 + tid;
                tws_u[idx] = ((const ull*)g_tw)[nc * 1024 + idx];
            }
            __syncthreads();
            #pragma unroll 4
            for (int n = 0; n < 64; n++) {
                ull tw = tws_u[n * 16 + m];
                float x0 = xs[(kg * 2) * 65 + n];
                float x1 = xs[(kg * 2 + 1) * 65 + n];
                acc0 = ffma2(pack2(x0, x0), tw, acc0);
                acc1 = ffma2(pack2(x1, x1), tw, acc1);
            }
            __syncthreads();
        }
        Ys_u[(kc * 32 + kg * 2) * 16 + m]     = acc0;
        Ys_u[(kc * 32 + kg * 2 + 1) * 16 + m] = acc1;
    }
    __syncthreads();

    // stage 2: xh[l][m] = sum_k wfwd[k][l][m] * Y[k][m]
    ull acc = 0ull;
    const float* wcol = g_wfwd + tid;   // tid = l*16+m -> [k][l][m] coalesced
    #pragma unroll 8
    for (int k = 0; k < NLAT; k++) {
        float wv = wcol[k * 256];
        acc = ffma2(pack2(wv, wv), Ys_u[k * 16 + m], acc);
    }
    float2 r = unpack2(acc);
    int b = bc >> 3, c = bc & 7;
    int l = tid >> 4;
    float2* zp = (float2*)(g_z + (size_t)b * 4096 + c * 512 + l * 32 + m * 2);
    *zp = make_float2(r.x, r.y);
}

// ---------------- GEMM: Cpart[64 x N] = A[64 x Kchunk] @ B[N x Kchunk]^T ----------------
// split-K partials only; no bias/activation here.
// mode 0: A=g_z (lda 4096), C=g_p1, N=8192, splitK=4 (chunk 1024)
// mode 1: A=g_h (lda 8192), C=g_p2, N=4096, splitK=8 (chunk 1024)
__global__ void __launch_bounds__(256, 4) k_gemm(int mode, const float* __restrict__ B)
{
    __shared__ __align__(16) float As[32 * 68];
    __shared__ __align__(16) float Bs[32 * 68];

    const float* A; float* C; int lda, N;
    if (mode == 0) { A = g_z; C = g_p1; lda = 4096; N = 8192; }
    else           { A = g_h; C = g_p2; lda = 8192; N = 4096; }
    const int kIters = 32;                       // 32 * 32 = 1024 K per split
    int tid  = threadIdx.x;
    int n0   = blockIdx.x * 64;
    int kOff = blockIdx.y * 1024;
    C += (size_t)blockIdx.y * 64 * N;

    int m0 = (tid & 15) * 4;
    int n4 = (tid >> 4) * 4;
    int row = tid >> 3;
    int kq  = (tid & 7) * 4;

    ull acc[4][2];
    #pragma unroll
    for (int i = 0; i < 4; i++) { acc[i][0] = 0ull; acc[i][1] = 0ull; }

    for (int it = 0; it < kIters; it++) {
        int k0 = kOff + it * 32;
        float4 avr[2], bvr[2];
        #pragma unroll
        for (int rr = 0; rr < 2; rr++) {
            int rrow = row + rr * 32;
            avr[rr] = *(const float4*)(A + (size_t)rrow * lda + k0 + kq);
            bvr[rr] = *(const float4*)(B + (size_t)(n0 + rrow) * lda + k0 + kq);
        }
        __syncthreads();
        #pragma unroll
        for (int rr = 0; rr < 2; rr++) {
            int rrow = row + rr * 32;
            As[(kq + 0) * 68 + rrow] = avr[rr].x;
            As[(kq + 1) * 68 + rrow] = avr[rr].y;
            As[(kq + 2) * 68 + rrow] = avr[rr].z;
            As[(kq + 3) * 68 + rrow] = avr[rr].w;
            Bs[(kq + 0) * 68 + rrow] = bvr[rr].x;
            Bs[(kq + 1) * 68 + rrow] = bvr[rr].y;
            Bs[(kq + 2) * 68 + rrow] = bvr[rr].z;
            Bs[(kq + 3) * 68 + rrow] = bvr[rr].w;
        }
        __syncthreads();
        #pragma unroll 8
        for (int k = 0; k < 32; k++) {
            float4 a = *(const float4*)&As[k * 68 + m0];
            ulonglong2 bu = *(const ulonglong2*)&Bs[k * 68 + n4];
            ull a0 = pack2(a.x, a.x), a1 = pack2(a.y, a.y);
            ull a2 = pack2(a.z, a.z), a3 = pack2(a.w, a.w);
            acc[0][0] = ffma2(a0, bu.x, acc[0][0]);
            acc[0][1] = ffma2(a0, bu.y, acc[0][1]);
            acc[1][0] = ffma2(a1, bu.x, acc[1][0]);
            acc[1][1] = ffma2(a1, bu.y, acc[1][1]);
            acc[2][0] = ffma2(a2, bu.x, acc[2][0]);
            acc[2][1] = ffma2(a2, bu.y, acc[2][1]);
            acc[3][0] = ffma2(a3, bu.x, acc[3][0]);
            acc[3][1] = ffma2(a3, bu.y, acc[3][1]);
        }
    }

    #pragma unroll
    for (int i = 0; i < 4; i++) {
        float2 v0 = unpack2(acc[i][0]);
        float2 v1 = unpack2(acc[i][1]);
        float4 o; o.x = v0.x; o.y = v0.y; o.z = v1.x; o.w = v1.y;
        *(float4*)(C + (size_t)(m0 + i) * N + n0 + n4) = o;
    }
}

// ---------------- epilogue 1: reduce 4 partials + bias + gelu -> g_h ----------------
__global__ void __launch_bounds__(256) k_epi1(const float* __restrict__ b0) {
    int i = blockIdx.x * 256 + threadIdx.x;          // float4 index, 131072 total
    const float4* p = (const float4*)g_p1;
    float4 s0 = p[i];
    float4 s1 = p[i + 131072];
    float4 s2 = p[i + 2 * 131072];
    float4 s3 = p[i + 3 * 131072];
    float4 bv = ((const float4*)b0)[i & 2047];       // col4 = i mod (8192/4)
    float4 o;
    o.x = gelu_exact(s0.x + s1.x + s2.x + s3.x + bv.x);
    o.y = gelu_exact(s0.y + s1.y + s2.y + s3.y + bv.y);
    o.z = gelu_exact(s0.z + s1.z + s2.z + s3.z + bv.z);
    o.w = gelu_exact(s0.w + s1.w + s2.w + s3.w + bv.w);
    ((float4*)g_h)[i] = o;
}

// ---------------- epilogue 2: reduce 8 partials -> g_ohf ----------------
__global__ void __launch_bounds__(256) k_epi2() {
    int i = blockIdx.x * 256 + threadIdx.x;          // float4 index, 65536 total
    const float4* p = (const float4*)g_p2;
    float4 s = p[i];
    #pragma unroll
    for (int sK = 1; sK < 8; sK++) {
        float4 v = p[i + sK * 65536];
        s.x += v.x; s.y += v.y; s.z += v.z; s.w += v.w;
    }
    ((float4*)g_ohf)[i] = s;
}

// ---------------- inverse: Legendre + inverse DFT + bypass + gelu ----------------
// one block per (b, k-quarter); 256 threads
__global__ void __launch_bounds__(256) k_inverse(const float* __restrict__ x,
    const float* __restrict__ cw, const float* __restrict__ cb,
    float* __restrict__ out)
{
    __shared__ __align__(16) ull xks_u[8 * 32 * 16];   // [c][k_local][m] complex, 32KB
    __shared__ float cws[64];
    __shared__ float cbs[8];

    int tid = threadIdx.x;
    int b   = blockIdx.x >> 2;
    int kq  = blockIdx.x & 3;

    if (tid < 64) cws[tid] = cw[tid];
    if (tid < 8)  cbs[tid] = cb[tid];

    // stage 2: xk[c][k][m] = sum_l oh[c][l][m] * pct[m][l][k]
    {
        int c  = tid >> 5;
        int kl = tid & 31;
        const float* p0 = g_ohf + (size_t)b * 4096 + c * 512;
        #pragma unroll 4
        for (int m = 0; m < 16; m++) {
            ull acc = 0ull;
            #pragma unroll
            for (int l = 0; l < 16; l++) {
                int off = l * 32 + m * 2;
                float orr = p0[off];
                float oi  = p0[off + 1];
                float pv  = g_pct[(m * 16 + l) * NLAT + kq * 32 + kl];
                acc = ffma2(pack2(pv, pv), pack2(orr, oi), acc);
            }
            xks_u[(c * 32 + kl) * 16 + m] = acc;
        }
    }
    __syncthreads();

    // stage 3: per longitude column n = tid
    int n = tid;
    ull itw_r[16];
    #pragma unroll
    for (int m = 0; m < 16; m++)
        itw_r[m] = ((const ull*)g_itw)[n * 16 + m];

    for (int kl = 0; kl < 32; kl++) {
        int k = kq * 32 + kl;
        float xv[8];
        #pragma unroll
        for (int c = 0; c < 8; c++)
            xv[c] = x[(((size_t)b * 8 + c) * NLAT + k) * NLON + n];
        #pragma unroll
        for (int o = 0; o < 8; o++) {
            ull acc = 0ull;
            #pragma unroll
            for (int m = 0; m < 16; m++)
                acc = ffma2(xks_u[(o * 32 + kl) * 16 + m], itw_r[m], acc);
            float2 ar = unpack2(acc);
            float spec = ar.x + ar.y;
            float byp = cbs[o];
            #pragma unroll
            for (int c = 0; c < 8; c++)
                byp = fmaf(xv[c], cws[o * 8 + c], byp);
            out[(((size_t)b * 8 + o) * NLAT + k) * NLON + n] = gelu_exact(spec + byp);
        }
    }
}

// ---------------- launch ----------------
extern "C" void kernel_launch(void* const* d_in, const int* in_sizes, int n_in,
                              void* d_out, int out_size) {
    const float* x  = (const float*)d_in[0];
    const float* w0 = (const float*)d_in[1];
    const float* b0 = (const float*)d_in[2];
    const float* w1 = (const float*)d_in[3];
    const float* cw = (const float*)d_in[4];
    const float* cb = (const float*)d_in[5];
    float* out = (float*)d_out;

    k_setup_leg<<<1, 128>>>();
    k_setup_tw<<<32, 256>>>();
    k_forward<<<NB * CIN, 256>>>(x);
    k_gemm<<<dim3(128, 4), 256>>>(0, w0);     // z @ w0^T partials (splitK=4)
    k_epi1<<<512, 256>>>(b0);                 // reduce + bias + gelu -> g_h
    k_gemm<<<dim3(64, 8), 256>>>(1, w1);      // h @ w1^T partials (splitK=8)
    k_epi2<<<256, 256>>>();                   // reduce -> g_ohf
    k_inverse<<<NB * 4, 256>>>(x, cw, cb, out);
}

// round 6
// speedup vs baseline: 1.9116x; 1.6810x over previous
#include <cuda_runtime.h>
#include <math.h>

typedef unsigned long long ull;

#define NB    64
#define CIN   8
#define COUT  8
#define NLAT  128
#define NLON  256
#define M0D   16
#define M1D   16

// ---------------- device scratch (no allocations allowed) ----------------
__device__ float  g_wfwd[NLAT * M0D * M1D];   // [k][l][m]  (wq*2pi/256 and CS sign folded in)
__device__ float  g_pct [M1D * M0D * NLAT];   // [m][l][k]  (CS sign folded in)
__device__ float2 g_tw  [NLON * M1D];         // fwd twiddles [n][m] = (cos th, -sin th)
__device__ float2 g_itw [NLON * M1D];         // inv twiddles [n][m] = (c, s)
__device__ float  g_z   [NB * 4096];          // forward spectral features
__device__ float  g_h   [NB * 8192];          // MLP hidden (post bias+gelu)
__device__ float  g_p1  [4 * NB * 8192];      // GEMM1 split-K partials
__device__ float  g_p2  [8 * NB * 4096];      // GEMM2 split-K partials
__device__ float  g_ohf [NB * 4096];          // reduced MLP output

// ---------------- helpers ----------------
__device__ __forceinline__ ull pack2(float a, float b) {
    ull d;
    asm("mov.b64 %0, {%1, %2};" : "=l"(d) : "r"(__float_as_uint(a)), "r"(__float_as_uint(b)));
    return d;
}
__device__ __forceinline__ ull ffma2(ull a, ull b, ull c) {
    ull d;
    asm("fma.rn.f32x2 %0, %1, %2, %3;" : "=l"(d) : "l"(a), "l"(b), "l"(c));
    return d;
}
__device__ __forceinline__ float2 unpack2(ull v) {
    unsigned lo, hi;
    asm("mov.b64 {%0, %1}, %2;" : "=r"(lo), "=r"(hi) : "l"(v));
    float2 r; r.x = __uint_as_float(lo); r.y = __uint_as_float(hi);
    return r;
}
__device__ __forceinline__ float gelu_exact(float x) {
    return 0.5f * x * (1.0f + erff(x * 0.70710678118654752440f));
}

// ---------------- setup: CC quadrature + Legendre tables ----------------
// rolling 2-register recurrence, shared sqrt coefficient tables, fp32 weights
__global__ void k_setup_leg() {
    __shared__ double sa[16 * 16], sb[16 * 16];   // [m][l] for l>=m+2
    __shared__ double sA1[17], sD[17];
    int j = threadIdx.x;
    const double PI = 3.14159265358979323846;
    if (j < 17) {
        sA1[j] = sqrt(2.0 * j + 1.0);
        sD[j]  = (j >= 1) ? sqrt((2.0 * j + 1.0) / (2.0 * j)) : 0.0;
    }
    if (j < 105) {   // enumerate (l >= 2, m <= l-2) pairs
        int l = 2, acc = 0;
        while (acc + (l - 1) <= j) { acc += (l - 1); l++; }
        int m = j - acc;
        sa[m * 16 + l] = sqrt((2.0 * l - 1.0) / (l - m) * (2.0 * l + 1.0) / (l + m));
        sb[m * 16 + l] = sqrt((l + m - 1.0) / (l - m) * (2.0 * l + 1.0) / (2.0 * l - 3.0) *
                              (l - m - 1.0) / (l + m));
    }
    __syncthreads();
    if (j >= NLAT) return;

    double x = -cos(PI * (double)j / 127.0);     // ct[j]
    // Clenshaw-Curtis weight (fp32 trig is plenty: ~1e-7)
    float tj = (float)(PI * (double)j / 127.0);
    float w = 2.0f / 127.0f;
    #pragma unroll 4
    for (int kk = 1; kk <= 63; kk++)
        w -= 2.0f * cosf(2.0f * (float)kk * tj) * (2.0f / 127.0f) / (4.0f * kk * kk - 1.0f);
    if (j == 0 || j == 127) w *= 0.5f;

    double s = sqrt(fmax(0.0, (1.0 + x) * (1.0 - x)));
    double diag[16];
    diag[0] = 1.0 / sqrt(4.0 * PI);
    #pragma unroll
    for (int l = 1; l < 16; l++) diag[l] = sD[l] * s * diag[l - 1];

    const double sc = 2.0 * PI / 256.0;
    for (int m = 0; m < 16; m++) {
        double sgn = (m & 1) ? -1.0 : 1.0;
        double pa = diag[m];
        {   // l = m
            double v = pa * sgn;
            g_wfwd[j * 256 + m * 16 + m]    = (float)(v * w * sc);
            g_pct[(m * 16 + m) * NLAT + j]  = (float)v;
        }
        if (m + 1 < 16) {
            double pb = sA1[m + 1] * x * pa;
            double v = pb * sgn;
            g_wfwd[j * 256 + (m + 1) * 16 + m]   = (float)(v * w * sc);
            g_pct[(m * 16 + m + 1) * NLAT + j]   = (float)v;
            for (int l = m + 2; l < 16; l++) {
                double pc = sa[m * 16 + l] * x * pb - sb[m * 16 + l] * pa;
                pa = pb; pb = pc;
                double vv = pc * sgn;
                g_wfwd[j * 256 + l * 16 + m]   = (float)(vv * w * sc);
                g_pct[(m * 16 + l) * NLAT + j] = (float)vv;
            }
        }
    }
}

__global__ void k_setup_tw() {
    int g = blockIdx.x * blockDim.x + threadIdx.x;   // 0..8191
    const double PI = 3.14159265358979323846;
    if (g < NLON * M1D) {
        int n = g >> 4, m = g & 15;
        double th = 2.0 * PI * (double)((m * n) & (NLON - 1)) / (double)NLON;
        g_tw[g] = make_float2((float)cos(th), (float)(-sin(th)));
    } else {
        int h = g - NLON * M1D;
        int n = h >> 4, m = h & 15;
        double th = 2.0 * PI * (double)((m * n) & (NLON - 1)) / (double)NLON;
        float c = (m == 0) ? 1.0f : (float)(2.0 * cos(th));
        float s = (m == 0) ? 0.0f : (float)(-2.0 * sin(th));
        g_itw[h] = make_float2(c, s);
    }
}

// ---------------- forward: 16-mode DFT + Legendre -> g_z ----------------
// one block per (b,c); 256 threads; x stored duplicated (no pack movs in inner loop)
__global__ void __launch_bounds__(256) k_forward(const float* __restrict__ x) {
    __shared__ __align__(16) ull xsd[32 * 64];   // (x,x) pairs [k_local][n_local], 16KB
    __shared__ __align__(16) ull tws_u[64 * 16]; // twiddle chunk [n_local][m], 8KB
    __shared__ __align__(16) ull Ys_u[NLAT * 16];// DFT output [k][m] complex, 16KB

    int bc  = blockIdx.x;
    int tid = threadIdx.x;
    int kg  = tid >> 4;          // 0..15 -> handles k_local = 2*kg, 2*kg+1
    int m   = tid & 15;
    const float* xb = x + (size_t)bc * NLAT * NLON;

    for (int kc = 0; kc < 4; kc++) {
        ull acc0 = 0ull, acc1 = 0ull;
        for (int nc = 0; nc < 4; nc++) {
            #pragma unroll
            for (int i = 0; i < 8; i++) {
                int idx = i * 256 + tid;
                int kl = idx >> 6, nn = idx & 63;
                float v = xb[(kc * 32 + kl) * NLON + nc * 64 + nn];
                xsd[kl * 64 + nn] = pack2(v, v);
            }
            #pragma unroll
            for (int i = 0; i < 4; i++) {
                int idx = i * 256 + tid;
                tws_u[idx] = ((const ull*)g_tw)[nc * 1024 + idx];
            }
            __syncthreads();
            #pragma unroll 8
            for (int n = 0; n < 64; n++) {
                ull tw = tws_u[n * 16 + m];
                acc0 = ffma2(xsd[(kg * 2) * 64 + n], tw, acc0);
                acc1 = ffma2(xsd[(kg * 2 + 1) * 64 + n], tw, acc1);
            }
            __syncthreads();
        }
        Ys_u[(kc * 32 + kg * 2) * 16 + m]     = acc0;
        Ys_u[(kc * 32 + kg * 2 + 1) * 16 + m] = acc1;
    }
    __syncthreads();

    // stage 2: xh[l][m] = sum_k wfwd[k][l][m] * Y[k][m]
    ull acc = 0ull;
    const float* wcol = g_wfwd + tid;
    #pragma unroll 8
    for (int k = 0; k < NLAT; k++) {
        float wv = wcol[k * 256];
        acc = ffma2(pack2(wv, wv), Ys_u[k * 16 + m], acc);
    }
    float2 r = unpack2(acc);
    int b = bc >> 3, c = bc & 7;
    int l = tid >> 4;
    float2* zp = (float2*)(g_z + (size_t)b * 4096 + c * 512 + l * 32 + m * 2);
    *zp = make_float2(r.x, r.y);
}

// ---------------- GEMM: double-buffered split-K partials ----------------
// mode 0: A=g_z (lda 4096), C=g_p1, N=8192, splitK=4. mode 1: A=g_h (lda 8192), C=g_p2, splitK=8.
__global__ void __launch_bounds__(256, 3) k_gemm(int mode, const float* __restrict__ B)
{
    __shared__ __align__(16) float As[2][32 * 68];
    __shared__ __align__(16) float Bs[2][32 * 68];

    const float* A; float* C; int lda, N;
    if (mode == 0) { A = g_z; C = g_p1; lda = 4096; N = 8192; }
    else           { A = g_h; C = g_p2; lda = 8192; N = 4096; }
    const int kIters = 32;                       // 32 * 32 = 1024 K per split
    int tid  = threadIdx.x;
    int n0   = blockIdx.x * 64;
    int kOff = blockIdx.y * 1024;
    C += (size_t)blockIdx.y * 64 * N;

    int m0  = (tid & 15) * 4;
    int n4  = (tid >> 4) * 4;
    int row = tid >> 3;
    int kq  = (tid & 7) * 4;

    const float* Ap0 = A + (size_t)row * lda + kOff + kq;
    const float* Ap1 = A + (size_t)(row + 32) * lda + kOff + kq;
    const float* Bp0 = B + (size_t)(n0 + row) * lda + kOff + kq;
    const float* Bp1 = B + (size_t)(n0 + row + 32) * lda + kOff + kq;

    float4 av0, av1, bv0, bv1;
    av0 = *(const float4*)Ap0; av1 = *(const float4*)Ap1;
    bv0 = *(const float4*)Bp0; bv1 = *(const float4*)Bp1;

    // store tile 0 into buffer 0
    {
        float* as = As[0]; float* bs = Bs[0];
        as[(kq + 0) * 68 + row] = av0.x; as[(kq + 1) * 68 + row] = av0.y;
        as[(kq + 2) * 68 + row] = av0.z; as[(kq + 3) * 68 + row] = av0.w;
        as[(kq + 0) * 68 + row + 32] = av1.x; as[(kq + 1) * 68 + row + 32] = av1.y;
        as[(kq + 2) * 68 + row + 32] = av1.z; as[(kq + 3) * 68 + row + 32] = av1.w;
        bs[(kq + 0) * 68 + row] = bv0.x; bs[(kq + 1) * 68 + row] = bv0.y;
        bs[(kq + 2) * 68 + row] = bv0.z; bs[(kq + 3) * 68 + row] = bv0.w;
        bs[(kq + 0) * 68 + row + 32] = bv1.x; bs[(kq + 1) * 68 + row + 32] = bv1.y;
        bs[(kq + 2) * 68 + row + 32] = bv1.z; bs[(kq + 3) * 68 + row + 32] = bv1.w;
    }

    ull acc[4][2];
    #pragma unroll
    for (int i = 0; i < 4; i++) { acc[i][0] = 0ull; acc[i][1] = 0ull; }

    for (int it = 0; it < kIters; it++) {
        if (it + 1 < kIters) {          // prefetch next tile into registers
            int off = (it + 1) * 32;
            av0 = *(const float4*)(Ap0 + off); av1 = *(const float4*)(Ap1 + off);
            bv0 = *(const float4*)(Bp0 + off); bv1 = *(const float4*)(Bp1 + off);
        }
        __syncthreads();                // tile `it` visible; prev readers of next buf done
        const float* as = As[it & 1];
        const float* bs = Bs[it & 1];
        #pragma unroll 8
        for (int k = 0; k < 32; k++) {
            float4 a = *(const float4*)&as[k * 68 + m0];
            ulonglong2 bu = *(const ulonglong2*)&bs[k * 68 + n4];
            ull a0 = pack2(a.x, a.x), a1 = pack2(a.y, a.y);
            ull a2 = pack2(a.z, a.z), a3 = pack2(a.w, a.w);
            acc[0][0] = ffma2(a0, bu.x, acc[0][0]);
            acc[0][1] = ffma2(a0, bu.y, acc[0][1]);
            acc[1][0] = ffma2(a1, bu.x, acc[1][0]);
            acc[1][1] = ffma2(a1, bu.y, acc[1][1]);
            acc[2][0] = ffma2(a2, bu.x, acc[2][0]);
            acc[2][1] = ffma2(a2, bu.y, acc[2][1]);
            acc[3][0] = ffma2(a3, bu.x, acc[3][0]);
            acc[3][1] = ffma2(a3, bu.y, acc[3][1]);
        }
        if (it + 1 < kIters) {          // stage next tile into the other buffer
            float* asn = As[(it + 1) & 1]; float* bsn = Bs[(it + 1) & 1];
            asn[(kq + 0) * 68 + row] = av0.x; asn[(kq + 1) * 68 + row] = av0.y;
            asn[(kq + 2) * 68 + row] = av0.z; asn[(kq + 3) * 68 + row] = av0.w;
            asn[(kq + 0) * 68 + row + 32] = av1.x; asn[(kq + 1) * 68 + row + 32] = av1.y;
            asn[(kq + 2) * 68 + row + 32] = av1.z; asn[(kq + 3) * 68 + row + 32] = av1.w;
            bsn[(kq + 0) * 68 + row] = bv0.x; bsn[(kq + 1) * 68 + row] = bv0.y;
            bsn[(kq + 2) * 68 + row] = bv0.z; bsn[(kq + 3) * 68 + row] = bv0.w;
            bsn[(kq + 0) * 68 + row + 32] = bv1.x; bsn[(kq + 1) * 68 + row + 32] = bv1.y;
            bsn[(kq + 2) * 68 + row + 32] = bv1.z; bsn[(kq + 3) * 68 + row + 32] = bv1.w;
        }
    }

    #pragma unroll
    for (int i = 0; i < 4; i++) {
        float2 v0 = unpack2(acc[i][0]);
        float2 v1 = unpack2(acc[i][1]);
        float4 o; o.x = v0.x; o.y = v0.y; o.z = v1.x; o.w = v1.y;
        *(float4*)(C + (size_t)(m0 + i) * N + n0 + n4) = o;
    }
}

// ---------------- epilogue 1: reduce 4 partials + bias + gelu -> g_h ----------------
__global__ void __launch_bounds__(256) k_epi1(const float* __restrict__ b0) {
    int i = blockIdx.x * 256 + threadIdx.x;          // float4 index, 131072 total
    const float4* p = (const float4*)g_p1;
    float4 s0 = p[i];
    float4 s1 = p[i + 131072];
    float4 s2 = p[i + 2 * 131072];
    float4 s3 = p[i + 3 * 131072];
    float4 bv = ((const float4*)b0)[i & 2047];
    float4 o;
    o.x = gelu_exact(s0.x + s1.x + s2.x + s3.x + bv.x);
    o.y = gelu_exact(s0.y + s1.y + s2.y + s3.y + bv.y);
    o.z = gelu_exact(s0.z + s1.z + s2.z + s3.z + bv.z);
    o.w = gelu_exact(s0.w + s1.w + s2.w + s3.w + bv.w);
    ((float4*)g_h)[i] = o;
}

// ---------------- epilogue 2: reduce 8 partials -> g_ohf ----------------
__global__ void __launch_bounds__(256) k_epi2() {
    int i = blockIdx.x * 256 + threadIdx.x;          // float4 index, 65536 total
    const float4* p = (const float4*)g_p2;
    float4 s = p[i];
    #pragma unroll
    for (int sK = 1; sK < 8; sK++) {
        float4 v = p[i + sK * 65536];
        s.x += v.x; s.y += v.y; s.z += v.z; s.w += v.w;
    }
    ((float4*)g_ohf)[i] = s;
}

// ---------------- inverse: Legendre + inverse DFT + bypass + gelu ----------------
__global__ void __launch_bounds__(256) k_inverse(const float* __restrict__ x,
    const float* __restrict__ cw, const float* __restrict__ cb,
    float* __restrict__ out)
{
    __shared__ __align__(16) ull xks_u[8 * 32 * 16];   // [c][k_local][m] complex, 32KB
    __shared__ float cws[64];
    __shared__ float cbs[8];

    int tid = threadIdx.x;
    int b   = blockIdx.x >> 2;
    int kq  = blockIdx.x & 3;

    if (tid < 64) cws[tid] = cw[tid];
    if (tid < 8)  cbs[tid] = cb[tid];

    // stage 2: xk[c][k][m] = sum_l oh[c][l][m] * pct[m][l][k]
    {
        int c  = tid >> 5;
        int kl = tid & 31;
        const float* p0 = g_ohf + (size_t)b * 4096 + c * 512;
        #pragma unroll 4
        for (int m = 0; m < 16; m++) {
            ull acc = 0ull;
            #pragma unroll
            for (int l = 0; l < 16; l++) {
                int off = l * 32 + m * 2;
                float pv = g_pct[(m * 16 + l) * NLAT + kq * 32 + kl];
                acc = ffma2(pack2(pv, pv), pack2(p0[off], p0[off + 1]), acc);
            }
            xks_u[(c * 32 + kl) * 16 + m] = acc;
        }
    }
    __syncthreads();

    // stage 3: per longitude column n = tid
    int n = tid;
    ull itw_r[16];
    #pragma unroll
    for (int m = 0; m < 16; m++)
        itw_r[m] = ((const ull*)g_itw)[n * 16 + m];

    for (int kl = 0; kl < 32; kl++) {
        int k = kq * 32 + kl;
        float xv[8];
        #pragma unroll
        for (int c = 0; c < 8; c++)
            xv[c] = x[(((size_t)b * 8 + c) * NLAT + k) * NLON + n];
        #pragma unroll
        for (int o = 0; o < 8; o++) {
            const ulonglong2* xrow = (const ulonglong2*)&xks_u[(o * 32 + kl) * 16];
            ull acc = 0ull;
            #pragma unroll
            for (int mp = 0; mp < 8; mp++) {
                ulonglong2 xv2 = xrow[mp];
                acc = ffma2(xv2.x, itw_r[2 * mp],     acc);
                acc = ffma2(xv2.y, itw_r[2 * mp + 1], acc);
            }
            float2 ar = unpack2(acc);
            float spec = ar.x + ar.y;
            float byp = cbs[o];
            #pragma unroll
            for (int c = 0; c < 8; c++)
                byp = fmaf(xv[c], cws[o * 8 + c], byp);
            out[(((size_t)b * 8 + o) * NLAT + k) * NLON + n] = gelu_exact(spec + byp);
        }
    }
}

// ---------------- launch ----------------
extern "C" void kernel_launch(void* const* d_in, const int* in_sizes, int n_in,
                              void* d_out, int out_size) {
    const float* x  = (const float*)d_in[0];
    const float* w0 = (const float*)d_in[1];
    const float* b0 = (const float*)d_in[2];
    const float* w1 = (const float*)d_in[3];
    const float* cw = (const float*)d_in[4];
    const float* cb = (const float*)d_in[5];
    float* out = (float*)d_out;

    k_setup_leg<<<1, 128>>>();
    k_setup_tw<<<32, 256>>>();
    k_forward<<<NB * CIN, 256>>>(x);
    k_gemm<<<dim3(128, 4), 256>>>(0, w0);     // z @ w0^T partials (splitK=4)
    k_epi1<<<512, 256>>>(b0);                 // reduce + bias + gelu -> g_h
    k_gemm<<<dim3(64, 8), 256>>>(1, w1);      // h @ w1^T partials (splitK=8)
    k_epi2<<<256, 256>>>();                   // reduce -> g_ohf
    k_inverse<<<NB * 4, 256>>>(x, cw, cb, out);
}

// round 11
// speedup vs baseline: 2.6957x; 1.4102x over previous
#include <cuda_runtime.h>
#include <cuda_bf16.h>
#include <math.h>

typedef unsigned long long ull;
typedef unsigned int uint;

#define NB    64
#define CIN   8
#define COUT  8
#define NLAT  128
#define NLON  256
#define M0D   16
#define M1D   16

// ---------------- device scratch ----------------
__device__ float  g_wfwd[NLAT * M0D * M1D];   // [k][l][m]
__device__ float  g_pct [M1D * M0D * NLAT];   // [m][l][k]
__device__ float2 g_tw  [NLON * M1D];
__device__ float2 g_itw [NLON * M1D];
__device__ __nv_bfloat16 g_zh[NB * 4096];     // z hi  [b][4096]
__device__ __nv_bfloat16 g_zl[NB * 4096];     // z lo
__device__ __nv_bfloat16 g_hh[NB * 8192];     // h hi  [b][8192]
__device__ __nv_bfloat16 g_hl[NB * 8192];     // h lo
__device__ float  g_p1[2 * NB * 8192];        // GEMM1 partials [sk][b][feat]
__device__ float  g_p2[4 * NB * 4096];        // GEMM2 partials [sk][b][feat]
__device__ float  g_ohf[NB * 4096];           // reduced MLP output [b][feat]

// ---------------- helpers ----------------
__device__ __forceinline__ ull pack2(float a, float b) {
    ull d;
    asm("mov.b64 %0, {%1, %2};" : "=l"(d) : "r"(__float_as_uint(a)), "r"(__float_as_uint(b)));
    return d;
}
__device__ __forceinline__ ull ffma2(ull a, ull b, ull c) {
    ull d;
    asm("fma.rn.f32x2 %0, %1, %2, %3;" : "=l"(d) : "l"(a), "l"(b), "l"(c));
    return d;
}
__device__ __forceinline__ float2 unpack2(ull v) {
    unsigned lo, hi;
    asm("mov.b64 {%0, %1}, %2;" : "=r"(lo), "=r"(hi) : "l"(v));
    float2 r; r.x = __uint_as_float(lo); r.y = __uint_as_float(hi);
    return r;
}
__device__ __forceinline__ float gelu_exact(float x) {
    return 0.5f * x * (1.0f + erff(x * 0.70710678118654752440f));
}
// pack: a -> LOW half, b -> HIGH half (bf16x2)
__device__ __forceinline__ uint cvtpack(float a, float b) {
    uint r;
    asm("cvt.rn.bf16x2.f32 %0, %1, %2;" : "=r"(r) : "f"(b), "f"(a));
    return r;
}
__device__ __forceinline__ float bf_lo(uint h) { return __uint_as_float(h << 16); }
__device__ __forceinline__ float bf_hi(uint h) { return __uint_as_float(h & 0xffff0000u); }

// mma.m16n8k16 bf16, fp32 accum
__device__ __forceinline__ void mma_bf16(float* c, const uint* a, uint b0, uint b1) {
    asm volatile("mma.sync.aligned.m16n8k16.row.col.f32.bf16.bf16.f32 "
        "{%0,%1,%2,%3}, {%4,%5,%6,%7}, {%8,%9}, {%0,%1,%2,%3};"
        : "+f"(c[0]), "+f"(c[1]), "+f"(c[2]), "+f"(c[3])
        : "r"(a[0]), "r"(a[1]), "r"(a[2]), "r"(a[3]), "r"(b0), "r"(b1));
}

// ---------------- setup: CC quadrature + Legendre tables (fp64, validated R6) ----------------
__global__ void k_setup_leg() {
    __shared__ double sa[16 * 16], sb[16 * 16];
    __shared__ double sA1[17], sD[17];
    int j = threadIdx.x;
    const double PI = 3.14159265358979323846;
    if (j < 17) {
        sA1[j] = sqrt(2.0 * j + 1.0);
        sD[j]  = (j >= 1) ? sqrt((2.0 * j + 1.0) / (2.0 * j)) : 0.0;
    }
    if (j < 105) {
        int l = 2, acc = 0;
        while (acc + (l - 1) <= j) { acc += (l - 1); l++; }
        int m = j - acc;
        sa[m * 16 + l] = sqrt((2.0 * l - 1.0) / (l - m) * (2.0 * l + 1.0) / (l + m));
        sb[m * 16 + l] = sqrt((l + m - 1.0) / (l - m) * (2.0 * l + 1.0) / (2.0 * l - 3.0) *
                              (l - m - 1.0) / (l + m));
    }
    __syncthreads();
    if (j >= NLAT) return;

    double x = -cos(PI * (double)j / 127.0);
    float tj = (float)(PI * (double)j / 127.0);
    float w = 2.0f / 127.0f;
    #pragma unroll 4
    for (int kk = 1; kk <= 63; kk++)
        w -= 2.0f * cosf(2.0f * (float)kk * tj) * (2.0f / 127.0f) / (4.0f * kk * kk - 1.0f);
    if (j == 0 || j == 127) w *= 0.5f;

    double s = sqrt(fmax(0.0, (1.0 + x) * (1.0 - x)));
    double diag[16];
    diag[0] = 1.0 / sqrt(4.0 * PI);
    #pragma unroll
    for (int l = 1; l < 16; l++) diag[l] = sD[l] * s * diag[l - 1];

    const double sc = 2.0 * PI / 256.0;
    for (int m = 0; m < 16; m++) {
        double sgn = (m & 1) ? -1.0 : 1.0;
        double pa = diag[m];
        {
            double v = pa * sgn;
            g_wfwd[j * 256 + m * 16 + m]    = (float)(v * w * sc);
            g_pct[(m * 16 + m) * NLAT + j]  = (float)v;
        }
        if (m + 1 < 16) {
            double pb = sA1[m + 1] * x * pa;
            double v = pb * sgn;
            g_wfwd[j * 256 + (m + 1) * 16 + m]   = (float)(v * w * sc);
            g_pct[(m * 16 + m + 1) * NLAT + j]   = (float)v;
            for (int l = m + 2; l < 16; l++) {
                double pc = sa[m * 16 + l] * x * pb - sb[m * 16 + l] * pa;
                pa = pb; pb = pc;
                double vv = pc * sgn;
                g_wfwd[j * 256 + l * 16 + m]   = (float)(vv * w * sc);
                g_pct[(m * 16 + l) * NLAT + j] = (float)vv;
            }
        }
    }
}

__global__ void k_setup_tw() {
    int g = blockIdx.x * blockDim.x + threadIdx.x;   // 0..8191
    const double PI = 3.14159265358979323846;
    if (g < NLON * M1D) {
        int n = g >> 4, m = g & 15;
        double th = 2.0 * PI * (double)((m * n) & (NLON - 1)) / (double)NLON;
        g_tw[g] = make_float2((float)cos(th), (float)(-sin(th)));
    } else {
        int h = g - NLON * M1D;
        int n = h >> 4, m = h & 15;
        double th = 2.0 * PI * (double)((m * n) & (NLON - 1)) / (double)NLON;
        float c = (m == 0) ? 1.0f : (float)(2.0 * cos(th));
        float s = (m == 0) ? 0.0f : (float)(-2.0 * sin(th));
        g_itw[h] = make_float2(c, s);
    }
}

// ---------------- forward: 16-mode DFT + Legendre -> g_zh/g_zl ----------------
__global__ void __launch_bounds__(256) k_forward(const float* __restrict__ x) {
    __shared__ __align__(16) ull xsd[32 * 64];
    __shared__ __align__(16) ull tws_u[64 * 16];
    __shared__ __align__(16) ull Ys_u[NLAT * 16];

    int bc  = blockIdx.x;
    int tid = threadIdx.x;
    int kg  = tid >> 4;
    int m   = tid & 15;
    const float* xb = x + (size_t)bc * NLAT * NLON;

    for (int kc = 0; kc < 4; kc++) {
        ull acc0 = 0ull, acc1 = 0ull;
        for (int nc = 0; nc < 4; nc++) {
            #pragma unroll
            for (int i = 0; i < 8; i++) {
                int idx = i * 256 + tid;
                int kl = idx >> 6, nn = idx & 63;
                float v = xb[(kc * 32 + kl) * NLON + nc * 64 + nn];
                xsd[kl * 64 + nn] = pack2(v, v);
            }
            #pragma unroll
            for (int i = 0; i < 4; i++) {
                int idx = i * 256 + tid;
                tws_u[idx] = ((const ull*)g_tw)[nc * 1024 + idx];
            }
            __syncthreads();
            #pragma unroll 8
            for (int n = 0; n < 64; n++) {
                ull tw = tws_u[n * 16 + m];
                acc0 = ffma2(xsd[(kg * 2) * 64 + n], tw, acc0);
                acc1 = ffma2(xsd[(kg * 2 + 1) * 64 + n], tw, acc1);
            }
            __syncthreads();
        }
        Ys_u[(kc * 32 + kg * 2) * 16 + m]     = acc0;
        Ys_u[(kc * 32 + kg * 2 + 1) * 16 + m] = acc1;
    }
    __syncthreads();

    ull acc = 0ull;
    const float* wcol = g_wfwd + tid;
    #pragma unroll 8
    for (int k = 0; k < NLAT; k++) {
        float wv = wcol[k * 256];
        acc = ffma2(pack2(wv, wv), Ys_u[k * 16 + m], acc);
    }
    float2 r = unpack2(acc);
    int b = bc >> 3, c = bc & 7;
    int l = tid >> 4;
    size_t fo = (size_t)b * 4096 + c * 512 + l * 32 + m * 2;
    uint hz = cvtpack(r.x, r.y);                               // re lo, im hi
    uint lz = cvtpack(r.x - bf_lo(hz), r.y - bf_hi(hz));
    *(uint*)&g_zh[fo] = hz;
    *(uint*)&g_zl[fo] = lz;
}

// ---------------- bf16-split HMMA GEMM ----------------
// Scratch globals bound IN DEVICE CODE via mode (host-side &g_zh is a shadow symbol — R8-R10 bug).
// mode 0: Act=g_z*,  P=g_p1, ldk=4096, Ntot=8192 (W=w0)
// mode 1: Act=g_h*,  P=g_p2, ldk=8192, Ntot=4096 (W=w1)
// C[b=64][feat] partials: Act[64 x K] @ W[Ntot x K]^T over K-chunk 2048.
// C = Ah*Wh + Al*Wh + Ah*Wl (bf16 2.5-term split, fp32 accum).
#define GEMM_SMEM_BYTES 61440

__global__ void __launch_bounds__(256) k_bgemm(int mode, const float* __restrict__ W)
{
    extern __shared__ __align__(16) __nv_bfloat16 sm[];
    __nv_bfloat16* WH = sm;            // 2 x 5120 halves (128 rows x 40)
    __nv_bfloat16* WL = sm + 10240;    // 2 x 5120
    __nv_bfloat16* AH = sm + 20480;    // 2 x 2560 (64 rows x 40)
    __nv_bfloat16* AL = sm + 25600;    // 2 x 2560

    const __nv_bfloat16* Ah_g; const __nv_bfloat16* Al_g;
    float* P; int ldk, Ntot;
    if (mode == 0) { Ah_g = g_zh; Al_g = g_zl; P = g_p1; ldk = 4096; Ntot = 8192; }
    else           { Ah_g = g_hh; Al_g = g_hl; P = g_p2; ldk = 8192; Ntot = 4096; }

    int tid = threadIdx.x, wid = tid >> 5, lane = tid & 31;
    int warpM = wid & 1;               // batch half (2 x 32 rows)
    int warpN = wid >> 1;              // feat 32-block (4)
    int g = lane >> 2, t = lane & 3;
    int tile = blockIdx.x;
    int kOff = blockIdx.y * 2048;
    float* part = P + (size_t)blockIdx.y * 64 * Ntot;

    const float* Wt = W + (size_t)(tile * 128) * ldk + kOff;
    int aRow = tid >> 2;               // 0..63 activation row (batch)
    int aKg  = (tid & 3) * 8;          // 0,8,16,24

    float c[2][4][4];
    #pragma unroll
    for (int i = 0; i < 2; i++)
        #pragma unroll
        for (int jj = 0; jj < 4; jj++)
            #pragma unroll
            for (int q = 0; q < 4; q++) c[i][jj][q] = 0.f;

    float4 wv[4];
    uint4  avh, avl;
    // prefetch chunk 0
    #pragma unroll
    for (int r = 0; r < 4; r++) {
        int idx = r * 256 + tid;
        wv[r] = *(const float4*)(Wt + (size_t)(idx >> 3) * ldk + ((idx & 7) * 4));
    }
    avh = *(const uint4*)(Ah_g + (size_t)aRow * ldk + kOff + aKg);
    avl = *(const uint4*)(Al_g + (size_t)aRow * ldk + kOff + aKg);
    // store chunk 0 into buffer 0
    {
        #pragma unroll
        for (int r = 0; r < 4; r++) {
            int idx = r * 256 + tid;
            int row = idx >> 3, kq = (idx & 7) * 4;
            uint h0 = cvtpack(wv[r].x, wv[r].y);
            uint h1 = cvtpack(wv[r].z, wv[r].w);
            uint l0 = cvtpack(wv[r].x - bf_lo(h0), wv[r].y - bf_hi(h0));
            uint l1 = cvtpack(wv[r].z - bf_lo(h1), wv[r].w - bf_hi(h1));
            *(uint2*)&WH[row * 40 + kq] = make_uint2(h0, h1);
            *(uint2*)&WL[row * 40 + kq] = make_uint2(l0, l1);
        }
        *(uint4*)&AH[aRow * 40 + aKg] = avh;
        *(uint4*)&AL[aRow * 40 + aKg] = avl;
    }

    const int ITERS = 64;              // 64 * 32 = 2048 K per split
    for (int it = 0; it < ITERS; it++) {
        if (it + 1 < ITERS) {
            int k0 = (it + 1) * 32;
            #pragma unroll
            for (int r = 0; r < 4; r++) {
                int idx = r * 256 + tid;
                wv[r] = *(const float4*)(Wt + (size_t)(idx >> 3) * ldk + k0 + ((idx & 7) * 4));
            }
            avh = *(const uint4*)(Ah_g + (size_t)aRow * ldk + kOff + k0 + aKg);
            avl = *(const uint4*)(Al_g + (size_t)aRow * ldk + kOff + k0 + aKg);
        }
        __syncthreads();
        const __nv_bfloat16* cWH = WH + (it & 1) * 5120;
        const __nv_bfloat16* cWL = WL + (it & 1) * 5120;
        const __nv_bfloat16* cAH = AH + (it & 1) * 2560;
        const __nv_bfloat16* cAL = AL + (it & 1) * 2560;
        #pragma unroll
        for (int ks = 0; ks < 2; ks++) {
            int kb = ks * 16 + t * 2;
            uint ah[2][4], al[2][4];
            #pragma unroll
            for (int mi = 0; mi < 2; mi++) {
                int r0 = (warpM * 32 + mi * 16 + g) * 40 + kb;
                int r1 = r0 + 8 * 40;
                ah[mi][0] = *(const uint*)&cAH[r0];
                ah[mi][1] = *(const uint*)&cAH[r1];
                ah[mi][2] = *(const uint*)&cAH[r0 + 8];
                ah[mi][3] = *(const uint*)&cAH[r1 + 8];
                al[mi][0] = *(const uint*)&cAL[r0];
                al[mi][1] = *(const uint*)&cAL[r1];
                al[mi][2] = *(const uint*)&cAL[r0 + 8];
                al[mi][3] = *(const uint*)&cAL[r1 + 8];
            }
            uint wh[4][2], wl[4][2];
            #pragma unroll
            for (int nj = 0; nj < 4; nj++) {
                int o = (warpN * 32 + nj * 8 + g) * 40 + kb;
                wh[nj][0] = *(const uint*)&cWH[o];
                wh[nj][1] = *(const uint*)&cWH[o + 8];
                wl[nj][0] = *(const uint*)&cWL[o];
                wl[nj][1] = *(const uint*)&cWL[o + 8];
            }
            #pragma unroll
            for (int mi = 0; mi < 2; mi++)
                #pragma unroll
                for (int nj = 0; nj < 4; nj++) {
                    mma_bf16(c[mi][nj], ah[mi], wh[nj][0], wh[nj][1]);
                    mma_bf16(c[mi][nj], al[mi], wh[nj][0], wh[nj][1]);
                    mma_bf16(c[mi][nj], ah[mi], wl[nj][0], wl[nj][1]);
                }
        }
        if (it + 1 < ITERS) {
            int nb = (it + 1) & 1;
            __nv_bfloat16* nWH = WH + nb * 5120;
            __nv_bfloat16* nWL = WL + nb * 5120;
            __nv_bfloat16* nAH = AH + nb * 2560;
            __nv_bfloat16* nAL = AL + nb * 2560;
            __syncthreads();
            #pragma unroll
            for (int r = 0; r < 4; r++) {
                int idx = r * 256 + tid;
                int row = idx >> 3, kq = (idx & 7) * 4;
                uint h0 = cvtpack(wv[r].x, wv[r].y);
                uint h1 = cvtpack(wv[r].z, wv[r].w);
                uint l0 = cvtpack(wv[r].x - bf_lo(h0), wv[r].y - bf_hi(h0));
                uint l1 = cvtpack(wv[r].z - bf_lo(h1), wv[r].w - bf_hi(h1));
                *(uint2*)&nWH[row * 40 + kq] = make_uint2(h0, h1);
                *(uint2*)&nWL[row * 40 + kq] = make_uint2(l0, l1);
            }
            *(uint4*)&nAH[aRow * 40 + aKg] = avh;
            *(uint4*)&nAL[aRow * 40 + aKg] = avl;
        }
    }

    // C write: row = batch, col = global feature
    #pragma unroll
    for (int mi = 0; mi < 2; mi++) {
        #pragma unroll
        for (int nj = 0; nj < 4; nj++) {
            int row = warpM * 32 + mi * 16 + g;
            int col = tile * 128 + warpN * 32 + nj * 8 + t * 2;
            *(float2*)&part[(size_t)row * Ntot + col]       = make_float2(c[mi][nj][0], c[mi][nj][1]);
            *(float2*)&part[(size_t)(row + 8) * Ntot + col] = make_float2(c[mi][nj][2], c[mi][nj][3]);
        }
    }
}

// ---------------- epi1: reduce 2 partials + bias + gelu -> g_hh/g_hl (elementwise) ----------
__global__ void __launch_bounds__(256) k_epi1(const float* __restrict__ b0) {
    int i = blockIdx.x * 256 + threadIdx.x;          // float4 index over [64][8192] = 131072
    const float4* p = (const float4*)g_p1;
    float4 s0 = p[i];
    float4 s1 = p[i + 131072];
    float4 bv = ((const float4*)b0)[i & 2047];       // feat4 = i mod 2048
    float f0 = gelu_exact(s0.x + s1.x + bv.x);
    float f1 = gelu_exact(s0.y + s1.y + bv.y);
    float f2 = gelu_exact(s0.z + s1.z + bv.z);
    float f3 = gelu_exact(s0.w + s1.w + bv.w);
    uint h0 = cvtpack(f0, f1), h1 = cvtpack(f2, f3);
    uint l0 = cvtpack(f0 - bf_lo(h0), f1 - bf_hi(h0));
    uint l1 = cvtpack(f2 - bf_lo(h1), f3 - bf_hi(h1));
    ((uint2*)g_hh)[i] = make_uint2(h0, h1);
    ((uint2*)g_hl)[i] = make_uint2(l0, l1);
}

// ---------------- epi2: reduce 4 partials -> g_ohf (elementwise) ----------------
__global__ void __launch_bounds__(256) k_epi2() {
    int i = blockIdx.x * 256 + threadIdx.x;          // float4 index over [64][4096] = 65536
    const float4* p = (const float4*)g_p2;
    float4 s = p[i];
    #pragma unroll
    for (int sK = 1; sK < 4; sK++) {
        float4 v = p[i + sK * 65536];
        s.x += v.x; s.y += v.y; s.z += v.z; s.w += v.w;
    }
    ((float4*)g_ohf)[i] = s;
}

// ---------------- inverse: Legendre + inverse DFT + bypass + gelu (validated R6) ----------
__global__ void __launch_bounds__(256) k_inverse(const float* __restrict__ x,
    const float* __restrict__ cw, const float* __restrict__ cb,
    float* __restrict__ out)
{
    __shared__ __align__(16) ull xks_u[8 * 32 * 16];
    __shared__ float cws[64];
    __shared__ float cbs[8];

    int tid = threadIdx.x;
    int b   = blockIdx.x >> 2;
    int kq  = blockIdx.x & 3;

    if (tid < 64) cws[tid] = cw[tid];
    if (tid < 8)  cbs[tid] = cb[tid];

    {
        int c  = tid >> 5;
        int kl = tid & 31;
        const float* p0 = g_ohf + (size_t)b * 4096 + c * 512;
        #pragma unroll 4
        for (int m = 0; m < 16; m++) {
            ull acc = 0ull;
            #pragma unroll
            for (int l = 0; l < 16; l++) {
                int off = l * 32 + m * 2;
                float pv = g_pct[(m * 16 + l) * NLAT + kq * 32 + kl];
                acc = ffma2(pack2(pv, pv), pack2(p0[off], p0[off + 1]), acc);
            }
            xks_u[(c * 32 + kl) * 16 + m] = acc;
        }
    }
    __syncthreads();

    int n = tid;
    ull itw_r[16];
    #pragma unroll
    for (int m = 0; m < 16; m++)
        itw_r[m] = ((const ull*)g_itw)[n * 16 + m];

    for (int kl = 0; kl < 32; kl++) {
        int k = kq * 32 + kl;
        float xv[8];
        #pragma unroll
        for (int c = 0; c < 8; c++)
            xv[c] = x[(((size_t)b * 8 + c) * NLAT + k) * NLON + n];
        #pragma unroll
        for (int o = 0; o < 8; o++) {
            const ulonglong2* xrow = (const ulonglong2*)&xks_u[(o * 32 + kl) * 16];
            ull acc = 0ull;
            #pragma unroll
            for (int mp = 0; mp < 8; mp++) {
                ulonglong2 xv2 = xrow[mp];
                acc = ffma2(xv2.x, itw_r[2 * mp],     acc);
                acc = ffma2(xv2.y, itw_r[2 * mp + 1], acc);
            }
            float2 ar = unpack2(acc);
            float spec = ar.x + ar.y;
            float byp = cbs[o];
            #pragma unroll
            for (int c = 0; c < 8; c++)
                byp = fmaf(xv[c], cws[o * 8 + c], byp);
            out[(((size_t)b * 8 + o) * NLAT + k) * NLON + n] = gelu_exact(spec + byp);
        }
    }
}

// ---------------- launch ----------------
extern "C" void kernel_launch(void* const* d_in, const int* in_sizes, int n_in,
                              void* d_out, int out_size) {
    const float* x  = (const float*)d_in[0];
    const float* w0 = (const float*)d_in[1];
    const float* b0 = (const float*)d_in[2];
    const float* w1 = (const float*)d_in[3];
    const float* cw = (const float*)d_in[4];
    const float* cb = (const float*)d_in[5];
    float* out = (float*)d_out;

    cudaFuncSetAttribute(k_bgemm, cudaFuncAttributeMaxDynamicSharedMemorySize, GEMM_SMEM_BYTES);

    k_setup_leg<<<1, 128>>>();
    k_setup_tw<<<32, 256>>>();
    k_forward<<<NB * CIN, 256>>>(x);
    // GEMM1: C[64][8192] = z[64][4096] @ w0[8192][4096]^T, splitK=2, 64 feat-tiles
    k_bgemm<<<dim3(64, 2), 256, GEMM_SMEM_BYTES>>>(0, w0);
    k_epi1<<<512, 256>>>(b0);
    // GEMM2: C[64][4096] = h[64][8192] @ w1[4096][8192]^T, splitK=4, 32 feat-tiles
    k_bgemm<<<dim3(32, 4), 256, GEMM_SMEM_BYTES>>>(1, w1);
    k_epi2<<<256, 256>>>();
    k_inverse<<<NB * 4, 256>>>(x, cw, cb, out);
}

// round 12
// speedup vs baseline: 2.9484x; 1.0937x over previous
#include <cuda_runtime.h>
#include <cuda_bf16.h>
#include <math.h>

typedef unsigned long long ull;
typedef unsigned int uint;

#define NB    64
#define CIN   8
#define COUT  8
#define NLAT  128
#define NLON  256
#define M0D   16
#define M1D   16

// ---------------- device scratch ----------------
__device__ float  g_wfwd[NLAT * M0D * M1D];   // [k][l][m]
__device__ float  g_pct [M1D * M0D * NLAT];   // [m][l][k]
__device__ float2 g_tw  [NLON * M1D];
__device__ float2 g_itw [NLON * M1D];
__device__ __nv_bfloat16 g_zh[NB * 4096];     // z hi  [b][4096]
__device__ __nv_bfloat16 g_zl[NB * 4096];     // z lo
__device__ __nv_bfloat16 g_hh[NB * 8192];     // h hi  [b][8192]
__device__ __nv_bfloat16 g_hl[NB * 8192];     // h lo
__device__ float  g_p1[4 * NB * 8192];        // GEMM1 partials [sk][b][feat]
__device__ float  g_p2[8 * NB * 4096];        // GEMM2 partials [sk][b][feat]
__device__ float  g_ohf[NB * 4096];           // reduced MLP output [b][feat]

// ---------------- helpers ----------------
__device__ __forceinline__ ull pack2(float a, float b) {
    ull d;
    asm("mov.b64 %0, {%1, %2};" : "=l"(d) : "r"(__float_as_uint(a)), "r"(__float_as_uint(b)));
    return d;
}
__device__ __forceinline__ ull ffma2(ull a, ull b, ull c) {
    ull d;
    asm("fma.rn.f32x2 %0, %1, %2, %3;" : "=l"(d) : "l"(a), "l"(b), "l"(c));
    return d;
}
__device__ __forceinline__ float2 unpack2(ull v) {
    unsigned lo, hi;
    asm("mov.b64 {%0, %1}, %2;" : "=r"(lo), "=r"(hi) : "l"(v));
    float2 r; r.x = __uint_as_float(lo); r.y = __uint_as_float(hi);
    return r;
}
__device__ __forceinline__ float gelu_exact(float x) {
    return 0.5f * x * (1.0f + erff(x * 0.70710678118654752440f));
}
// pack: a -> LOW half, b -> HIGH half (bf16x2)
__device__ __forceinline__ uint cvtpack(float a, float b) {
    uint r;
    asm("cvt.rn.bf16x2.f32 %0, %1, %2;" : "=r"(r) : "f"(b), "f"(a));
    return r;
}
__device__ __forceinline__ float bf_lo(uint h) { return __uint_as_float(h << 16); }
__device__ __forceinline__ float bf_hi(uint h) { return __uint_as_float(h & 0xffff0000u); }

// mma.m16n8k16 bf16, fp32 accum
__device__ __forceinline__ void mma_bf16(float* c, const uint* a, uint b0, uint b1) {
    asm volatile("mma.sync.aligned.m16n8k16.row.col.f32.bf16.bf16.f32 "
        "{%0,%1,%2,%3}, {%4,%5,%6,%7}, {%8,%9}, {%0,%1,%2,%3};"
        : "+f"(c[0]), "+f"(c[1]), "+f"(c[2]), "+f"(c[3])
        : "r"(a[0]), "r"(a[1]), "r"(a[2]), "r"(a[3]), "r"(b0), "r"(b1));
}

// ---------------- setup: CC quadrature + Legendre tables (fp64, validated) ----------------
__global__ void k_setup_leg() {
    __shared__ double sa[16 * 16], sb[16 * 16];
    __shared__ double sA1[17], sD[17];
    int j = threadIdx.x;
    const double PI = 3.14159265358979323846;
    if (j < 17) {
        sA1[j] = sqrt(2.0 * j + 1.0);
        sD[j]  = (j >= 1) ? sqrt((2.0 * j + 1.0) / (2.0 * j)) : 0.0;
    }
    if (j < 105) {
        int l = 2, acc = 0;
        while (acc + (l - 1) <= j) { acc += (l - 1); l++; }
        int m = j - acc;
        sa[m * 16 + l] = sqrt((2.0 * l - 1.0) / (l - m) * (2.0 * l + 1.0) / (l + m));
        sb[m * 16 + l] = sqrt((l + m - 1.0) / (l - m) * (2.0 * l + 1.0) / (2.0 * l - 3.0) *
                              (l - m - 1.0) / (l + m));
    }
    __syncthreads();
    if (j >= NLAT) return;

    double x = -cos(PI * (double)j / 127.0);
    float tj = (float)(PI * (double)j / 127.0);
    float w = 2.0f / 127.0f;
    #pragma unroll 4
    for (int kk = 1; kk <= 63; kk++)
        w -= 2.0f * cosf(2.0f * (float)kk * tj) * (2.0f / 127.0f) / (4.0f * kk * kk - 1.0f);
    if (j == 0 || j == 127) w *= 0.5f;

    double s = sqrt(fmax(0.0, (1.0 + x) * (1.0 - x)));
    double diag[16];
    diag[0] = 1.0 / sqrt(4.0 * PI);
    #pragma unroll
    for (int l = 1; l < 16; l++) diag[l] = sD[l] * s * diag[l - 1];

    const double sc = 2.0 * PI / 256.0;
    for (int m = 0; m < 16; m++) {
        double sgn = (m & 1) ? -1.0 : 1.0;
        double pa = diag[m];
        {
            double v = pa * sgn;
            g_wfwd[j * 256 + m * 16 + m]    = (float)(v * w * sc);
            g_pct[(m * 16 + m) * NLAT + j]  = (float)v;
        }
        if (m + 1 < 16) {
            double pb = sA1[m + 1] * x * pa;
            double v = pb * sgn;
            g_wfwd[j * 256 + (m + 1) * 16 + m]   = (float)(v * w * sc);
            g_pct[(m * 16 + m + 1) * NLAT + j]   = (float)v;
            for (int l = m + 2; l < 16; l++) {
                double pc = sa[m * 16 + l] * x * pb - sb[m * 16 + l] * pa;
                pa = pb; pb = pc;
                double vv = pc * sgn;
                g_wfwd[j * 256 + l * 16 + m]   = (float)(vv * w * sc);
                g_pct[(m * 16 + l) * NLAT + j] = (float)vv;
            }
        }
    }
}

__global__ void k_setup_tw() {
    int g = blockIdx.x * blockDim.x + threadIdx.x;   // 0..8191
    const double PI = 3.14159265358979323846;
    if (g < NLON * M1D) {
        int n = g >> 4, m = g & 15;
        double th = 2.0 * PI * (double)((m * n) & (NLON - 1)) / (double)NLON;
        g_tw[g] = make_float2((float)cos(th), (float)(-sin(th)));
    } else {
        int h = g - NLON * M1D;
        int n = h >> 4, m = h & 15;
        double th = 2.0 * PI * (double)((m * n) & (NLON - 1)) / (double)NLON;
        float c = (m == 0) ? 1.0f : (float)(2.0 * cos(th));
        float s = (m == 0) ? 0.0f : (float)(-2.0 * sin(th));
        g_itw[h] = make_float2(c, s);
    }
}

// ---------------- forward: 16-mode DFT + Legendre -> g_zh/g_zl ----------------
// thread = (k, m-half): 8 independent ffma2 chains, broadcast twiddle LDS.128.
__global__ void __launch_bounds__(256) k_forward(const float* __restrict__ x) {
    __shared__ __align__(16) char smraw[33280 + 8192];
    float* xs  = (float*)smraw;                 // [128][65]  (stage 1)
    ull*   Ys  = (ull*)smraw;                   // [128][16]  (overlay, stage 2)
    ull*   tws = (ull*)(smraw + 33280);         // [64][16]

    int bc  = blockIdx.x;
    int tid = threadIdx.x;
    int kk  = tid >> 1;             // 0..127 latitude row
    int mh  = (tid & 1) * 8;        // m base: 0 or 8
    const float* xb = x + (size_t)bc * NLAT * NLON;

    ull acc[8];
    #pragma unroll
    for (int j = 0; j < 8; j++) acc[j] = 0ull;

    for (int nc = 0; nc < 4; nc++) {
        #pragma unroll
        for (int i = 0; i < 32; i++) {
            int idx = i * 256 + tid;
            int k = idx >> 6, n = idx & 63;
            xs[k * 65 + n] = xb[k * 256 + nc * 64 + n];
        }
        #pragma unroll
        for (int i = 0; i < 4; i++) {
            int idx = i * 256 + tid;
            tws[idx] = ((const ull*)g_tw)[nc * 1024 + idx];
        }
        __syncthreads();
        #pragma unroll 4
        for (int n = 0; n < 64; n++) {
            float xv = xs[kk * 65 + n];
            ull xp = pack2(xv, xv);
            const ulonglong2* tp = (const ulonglong2*)&tws[n * 16 + mh];
            ulonglong2 t0 = tp[0], t1 = tp[1], t2 = tp[2], t3 = tp[3];
            acc[0] = ffma2(xp, t0.x, acc[0]);
            acc[1] = ffma2(xp, t0.y, acc[1]);
            acc[2] = ffma2(xp, t1.x, acc[2]);
            acc[3] = ffma2(xp, t1.y, acc[3]);
            acc[4] = ffma2(xp, t2.x, acc[4]);
            acc[5] = ffma2(xp, t2.y, acc[5]);
            acc[6] = ffma2(xp, t3.x, acc[6]);
            acc[7] = ffma2(xp, t3.y, acc[7]);
        }
        __syncthreads();
    }

    // write Y[k][m] (overlays xs; all stage-1 reads completed at last sync)
    #pragma unroll
    for (int j = 0; j < 8; j++)
        Ys[kk * 16 + mh + j] = acc[j];
    __syncthreads();

    // stage 2: xh[l][m] = sum_k wfwd[k][l][m] * Y[k][m]
    int m = tid & 15;
    ull acc2 = 0ull;
    const float* wcol = g_wfwd + tid;
    #pragma unroll 8
    for (int k = 0; k < NLAT; k++) {
        float wv = wcol[k * 256];
        acc2 = ffma2(pack2(wv, wv), Ys[k * 16 + m], acc2);
    }
    float2 r = unpack2(acc2);
    int b = bc >> 3, c = bc & 7;
    int l = tid >> 4;
    size_t fo = (size_t)b * 4096 + c * 512 + l * 32 + m * 2;
    uint hz = cvtpack(r.x, r.y);                               // re lo, im hi
    uint lz = cvtpack(r.x - bf_lo(hz), r.y - bf_hi(hz));
    *(uint*)&g_zh[fo] = hz;
    *(uint*)&g_zl[fo] = lz;
}

// ---------------- bf16-split HMMA GEMM ----------------
// mode 0: Act=g_z*, P=g_p1, ldk=4096, Ntot=8192 (W=w0), grid (64,4)
// mode 1: Act=g_h*, P=g_p2, ldk=8192, Ntot=4096 (W=w1), grid (32,8)
// C[b=64][feat] partials: Act[64 x K] @ W[Ntot x K]^T over K-chunk 1024.
// C = Ah*Wh + Al*Wh + Ah*Wl (bf16 2.5-term split, fp32 accum).
#define GEMM_SMEM_BYTES 61440

__global__ void __launch_bounds__(256) k_bgemm(int mode, const float* __restrict__ W)
{
    extern __shared__ __align__(16) __nv_bfloat16 sm[];
    __nv_bfloat16* WH = sm;            // 2 x 5120 halves (128 rows x 40)
    __nv_bfloat16* WL = sm + 10240;    // 2 x 5120
    __nv_bfloat16* AH = sm + 20480;    // 2 x 2560 (64 rows x 40)
    __nv_bfloat16* AL = sm + 25600;    // 2 x 2560

    const __nv_bfloat16* Ah_g; const __nv_bfloat16* Al_g;
    float* P; int ldk, Ntot;
    if (mode == 0) { Ah_g = g_zh; Al_g = g_zl; P = g_p1; ldk = 4096; Ntot = 8192; }
    else           { Ah_g = g_hh; Al_g = g_hl; P = g_p2; ldk = 8192; Ntot = 4096; }

    int tid = threadIdx.x, wid = tid >> 5, lane = tid & 31;
    int warpM = wid & 1;               // batch half (2 x 32 rows)
    int warpN = wid >> 1;              // feat 32-block (4)
    int g = lane >> 2, t = lane & 3;
    int tile = blockIdx.x;
    int kOff = blockIdx.y * 1024;
    float* part = P + (size_t)blockIdx.y * 64 * Ntot;

    const float* Wt = W + (size_t)(tile * 128) * ldk + kOff;
    int aRow = tid >> 2;               // 0..63 activation row (batch)
    int aKg  = (tid & 3) * 8;          // 0,8,16,24

    float c[2][4][4];
    #pragma unroll
    for (int i = 0; i < 2; i++)
        #pragma unroll
        for (int jj = 0; jj < 4; jj++)
            #pragma unroll
            for (int q = 0; q < 4; q++) c[i][jj][q] = 0.f;

    float4 wv[4];
    uint4  avh, avl;
    // prefetch chunk 0
    #pragma unroll
    for (int r = 0; r < 4; r++) {
        int idx = r * 256 + tid;
        wv[r] = *(const float4*)(Wt + (size_t)(idx >> 3) * ldk + ((idx & 7) * 4));
    }
    avh = *(const uint4*)(Ah_g + (size_t)aRow * ldk + kOff + aKg);
    avl = *(const uint4*)(Al_g + (size_t)aRow * ldk + kOff + aKg);
    // store chunk 0 into buffer 0
    {
        #pragma unroll
        for (int r = 0; r < 4; r++) {
            int idx = r * 256 + tid;
            int row = idx >> 3, kq = (idx & 7) * 4;
            uint h0 = cvtpack(wv[r].x, wv[r].y);
            uint h1 = cvtpack(wv[r].z, wv[r].w);
            uint l0 = cvtpack(wv[r].x - bf_lo(h0), wv[r].y - bf_hi(h0));
            uint l1 = cvtpack(wv[r].z - bf_lo(h1), wv[r].w - bf_hi(h1));
            *(uint2*)&WH[row * 40 + kq] = make_uint2(h0, h1);
            *(uint2*)&WL[row * 40 + kq] = make_uint2(l0, l1);
        }
        *(uint4*)&AH[aRow * 40 + aKg] = avh;
        *(uint4*)&AL[aRow * 40 + aKg] = avl;
    }

    const int ITERS = 32;              // 32 * 32 = 1024 K per split
    for (int it = 0; it < ITERS; it++) {
        if (it + 1 < ITERS) {
            int k0 = (it + 1) * 32;
            #pragma unroll
            for (int r = 0; r < 4; r++) {
                int idx = r * 256 + tid;
                wv[r] = *(const float4*)(Wt + (size_t)(idx >> 3) * ldk + k0 + ((idx & 7) * 4));
            }
            avh = *(const uint4*)(Ah_g + (size_t)aRow * ldk + kOff + k0 + aKg);
            avl = *(const uint4*)(Al_g + (size_t)aRow * ldk + kOff + k0 + aKg);
        }
        __syncthreads();
        const __nv_bfloat16* cWH = WH + (it & 1) * 5120;
        const __nv_bfloat16* cWL = WL + (it & 1) * 5120;
        const __nv_bfloat16* cAH = AH + (it & 1) * 2560;
        const __nv_bfloat16* cAL = AL + (it & 1) * 2560;
        #pragma unroll
        for (int ks = 0; ks < 2; ks++) {
            int kb = ks * 16 + t * 2;
            uint ah[2][4], al[2][4];
            #pragma unroll
            for (int mi = 0; mi < 2; mi++) {
                int r0 = (warpM * 32 + mi * 16 + g) * 40 + kb;
                int r1 = r0 + 8 * 40;
                ah[mi][0] = *(const uint*)&cAH[r0];
                ah[mi][1] = *(const uint*)&cAH[r1];
                ah[mi][2] = *(const uint*)&cAH[r0 + 8];
                ah[mi][3] = *(const uint*)&cAH[r1 + 8];
                al[mi][0] = *(const uint*)&cAL[r0];
                al[mi][1] = *(const uint*)&cAL[r1];
                al[mi][2] = *(const uint*)&cAL[r0 + 8];
                al[mi][3] = *(const uint*)&cAL[r1 + 8];
            }
            uint wh[4][2], wl[4][2];
            #pragma unroll
            for (int nj = 0; nj < 4; nj++) {
                int o = (warpN * 32 + nj * 8 + g) * 40 + kb;
                wh[nj][0] = *(const uint*)&cWH[o];
                wh[nj][1] = *(const uint*)&cWH[o + 8];
                wl[nj][0] = *(const uint*)&cWL[o];
                wl[nj][1] = *(const uint*)&cWL[o + 8];
            }
            #pragma unroll
            for (int mi = 0; mi < 2; mi++)
                #pragma unroll
                for (int nj = 0; nj < 4; nj++) {
                    mma_bf16(c[mi][nj], ah[mi], wh[nj][0], wh[nj][1]);
                    mma_bf16(c[mi][nj], al[mi], wh[nj][0], wh[nj][1]);
                    mma_bf16(c[mi][nj], ah[mi], wl[nj][0], wl[nj][1]);
                }
        }
        if (it + 1 < ITERS) {
            int nb = (it + 1) & 1;
            __nv_bfloat16* nWH = WH + nb * 5120;
            __nv_bfloat16* nWL = WL + nb * 5120;
            __nv_bfloat16* nAH = AH + nb * 2560;
            __nv_bfloat16* nAL = AL + nb * 2560;
            __syncthreads();
            #pragma unroll
            for (int r = 0; r < 4; r++) {
                int idx = r * 256 + tid;
                int row = idx >> 3, kq = (idx & 7) * 4;
                uint h0 = cvtpack(wv[r].x, wv[r].y);
                uint h1 = cvtpack(wv[r].z, wv[r].w);
                uint l0 = cvtpack(wv[r].x - bf_lo(h0), wv[r].y - bf_hi(h0));
                uint l1 = cvtpack(wv[r].z - bf_lo(h1), wv[r].w - bf_hi(h1));
                *(uint2*)&nWH[row * 40 + kq] = make_uint2(h0, h1);
                *(uint2*)&nWL[row * 40 + kq] = make_uint2(l0, l1);
            }
            *(uint4*)&nAH[aRow * 40 + aKg] = avh;
            *(uint4*)&nAL[aRow * 40 + aKg] = avl;
        }
    }

    // C write: row = batch, col = global feature
    #pragma unroll
    for (int mi = 0; mi < 2; mi++) {
        #pragma unroll
        for (int nj = 0; nj < 4; nj++) {
            int row = warpM * 32 + mi * 16 + g;
            int col = tile * 128 + warpN * 32 + nj * 8 + t * 2;
            *(float2*)&part[(size_t)row * Ntot + col]       = make_float2(c[mi][nj][0], c[mi][nj][1]);
            *(float2*)&part[(size_t)(row + 8) * Ntot + col] = make_float2(c[mi][nj][2], c[mi][nj][3]);
        }
    }
}

// ---------------- epi1: reduce 4 partials + bias + gelu -> g_hh/g_hl (elementwise) ----------
__global__ void __launch_bounds__(256) k_epi1(const float* __restrict__ b0) {
    int i = blockIdx.x * 256 + threadIdx.x;          // float4 index over [64][8192] = 131072
    const float4* p = (const float4*)g_p1;
    float4 s0 = p[i];
    #pragma unroll
    for (int sk = 1; sk < 4; sk++) {
        float4 v = p[i + sk * 131072];
        s0.x += v.x; s0.y += v.y; s0.z += v.z; s0.w += v.w;
    }
    float4 bv = ((const float4*)b0)[i & 2047];       // feat4 = i mod 2048
    float f0 = gelu_exact(s0.x + bv.x);
    float f1 = gelu_exact(s0.y + bv.y);
    float f2 = gelu_exact(s0.z + bv.z);
    float f3 = gelu_exact(s0.w + bv.w);
    uint h0 = cvtpack(f0, f1), h1 = cvtpack(f2, f3);
    uint l0 = cvtpack(f0 - bf_lo(h0), f1 - bf_hi(h0));
    uint l1 = cvtpack(f2 - bf_lo(h1), f3 - bf_hi(h1));
    ((uint2*)g_hh)[i] = make_uint2(h0, h1);
    ((uint2*)g_hl)[i] = make_uint2(l0, l1);
}

// ---------------- epi2: reduce 8 partials -> g_ohf (elementwise) ----------------
__global__ void __launch_bounds__(256) k_epi2() {
    int i = blockIdx.x * 256 + threadIdx.x;          // float4 index over [64][4096] = 65536
    const float4* p = (const float4*)g_p2;
    float4 s = p[i];
    #pragma unroll
    for (int sK = 1; sK < 8; sK++) {
        float4 v = p[i + sK * 65536];
        s.x += v.x; s.y += v.y; s.z += v.z; s.w += v.w;
    }
    ((float4*)g_ohf)[i] = s;
}

// ---------------- inverse: Legendre + inverse DFT + bypass + gelu (validated) ----------
__global__ void __launch_bounds__(256) k_inverse(const float* __restrict__ x,
    const float* __restrict__ cw, const float* __restrict__ cb,
    float* __restrict__ out)
{
    __shared__ __align__(16) ull xks_u[8 * 32 * 16];
    __shared__ float cws[64];
    __shared__ float cbs[8];

    int tid = threadIdx.x;
    int b   = blockIdx.x >> 2;
    int kq  = blockIdx.x & 3;

    if (tid < 64) cws[tid] = cw[tid];
    if (tid < 8)  cbs[tid] = cb[tid];

    {
        int c  = tid >> 5;
        int kl = tid & 31;
        const float* p0 = g_ohf + (size_t)b * 4096 + c * 512;
        #pragma unroll 4
        for (int m = 0; m < 16; m++) {
            ull acc = 0ull;
            #pragma unroll
            for (int l = 0; l < 16; l++) {
                int off = l * 32 + m * 2;
                float pv = g_pct[(m * 16 + l) * NLAT + kq * 32 + kl];
                acc = ffma2(pack2(pv, pv), pack2(p0[off], p0[off + 1]), acc);
            }
            xks_u[(c * 32 + kl) * 16 + m] = acc;
        }
    }
    __syncthreads();

    int n = tid;
    ull itw_r[16];
    #pragma unroll
    for (int m = 0; m < 16; m++)
        itw_r[m] = ((const ull*)g_itw)[n * 16 + m];

    for (int kl = 0; kl < 32; kl++) {
        int k = kq * 32 + kl;
        float xv[8];
        #pragma unroll
        for (int c = 0; c < 8; c++)
            xv[c] = x[(((size_t)b * 8 + c) * NLAT + k) * NLON + n];
        #pragma unroll
        for (int o = 0; o < 8; o++) {
            const ulonglong2* xrow = (const ulonglong2*)&xks_u[(o * 32 + kl) * 16];
            ull acc = 0ull;
            #pragma unroll
            for (int mp = 0; mp < 8; mp++) {
                ulonglong2 xv2 = xrow[mp];
                acc = ffma2(xv2.x, itw_r[2 * mp],     acc);
                acc = ffma2(xv2.y, itw_r[2 * mp + 1], acc);
            }
            float2 ar = unpack2(acc);
            float spec = ar.x + ar.y;
            float byp = cbs[o];
            #pragma unroll
            for (int c = 0; c < 8; c++)
                byp = fmaf(xv[c], cws[o * 8 + c], byp);
            out[(((size_t)b * 8 + o) * NLAT + k) * NLON + n] = gelu_exact(spec + byp);
        }
    }
}

// ---------------- launch ----------------
extern "C" void kernel_launch(void* const* d_in, const int* in_sizes, int n_in,
                              void* d_out, int out_size) {
    const float* x  = (const float*)d_in[0];
    const float* w0 = (const float*)d_in[1];
    const float* b0 = (const float*)d_in[2];
    const float* w1 = (const float*)d_in[3];
    const float* cw = (const float*)d_in[4];
    const float* cb = (const float*)d_in[5];
    float* out = (float*)d_out;

    cudaFuncSetAttribute(k_bgemm, cudaFuncAttributeMaxDynamicSharedMemorySize, GEMM_SMEM_BYTES);

    k_setup_leg<<<1, 128>>>();
    k_setup_tw<<<32, 256>>>();
    k_forward<<<NB * CIN, 256>>>(x);
    // GEMM1: C[64][8192] = z[64][4096] @ w0[8192][4096]^T, splitK=4, 64 feat-tiles
    k_bgemm<<<dim3(64, 4), 256, GEMM_SMEM_BYTES>>>(0, w0);
    k_epi1<<<512, 256>>>(b0);
    // GEMM2: C[64][4096] = h[64][8192] @ w1[4096][8192]^T, splitK=8, 32 feat-tiles
    k_bgemm<<<dim3(32, 8), 256, GEMM_SMEM_BYTES>>>(1, w1);
    k_epi2<<<256, 256>>>();
    k_inverse<<<NB * 4, 256>>>(x, cw, cb, out);
}

// round 14
// speedup vs baseline: 3.3510x; 1.1365x over previous
#include <cuda_runtime.h>
#include <cuda_bf16.h>
#include <math.h>

typedef unsigned long long ull;
typedef unsigned int uint;

#define NB    64
#define CIN   8
#define COUT  8
#define NLAT  128
#define NLON  256
#define M0D   16
#define M1D   16

// ---------------- device scratch ----------------
__device__ float  g_wfwd[NLAT * M0D * M1D];   // [k][l][m]
__device__ float  g_pct [M1D * M0D * NLAT];   // [m][l][k]
__device__ float2 g_tw  [NLON * M1D];
__device__ float2 g_itw [NLON * M1D];
__device__ __nv_bfloat16 g_zh[NB * 4096];     // z hi  [b][4096]
__device__ __nv_bfloat16 g_zl[NB * 4096];     // z lo
__device__ __nv_bfloat16 g_hh[NB * 8192];     // h hi  [b][8192]
__device__ __nv_bfloat16 g_hl[NB * 8192];     // h lo
__device__ float  g_p1[8 * NB * 8192];        // GEMM1 partials [sk][b][feat]
__device__ float  g_p2[16 * NB * 4096];       // GEMM2 partials [sk][b][feat]
__device__ float  g_ohf[NB * 4096];           // reduced MLP output [b][feat]

// ---------------- helpers ----------------
__device__ __forceinline__ ull pack2(float a, float b) {
    ull d;
    asm("mov.b64 %0, {%1, %2};" : "=l"(d) : "r"(__float_as_uint(a)), "r"(__float_as_uint(b)));
    return d;
}
__device__ __forceinline__ ull ffma2(ull a, ull b, ull c) {
    ull d;
    asm("fma.rn.f32x2 %0, %1, %2, %3;" : "=l"(d) : "l"(a), "l"(b), "l"(c));
    return d;
}
__device__ __forceinline__ float2 unpack2(ull v) {
    unsigned lo, hi;
    asm("mov.b64 {%0, %1}, %2;" : "=r"(lo), "=r"(hi) : "l"(v));
    float2 r; r.x = __uint_as_float(lo); r.y = __uint_as_float(hi);
    return r;
}
__device__ __forceinline__ float gelu_exact(float x) {
    return 0.5f * x * (1.0f + erff(x * 0.70710678118654752440f));
}
// pack: a -> LOW half, b -> HIGH half (bf16x2)
__device__ __forceinline__ uint cvtpack(float a, float b) {
    uint r;
    asm("cvt.rn.bf16x2.f32 %0, %1, %2;" : "=r"(r) : "f"(b), "f"(a));
    return r;
}
__device__ __forceinline__ float bf_lo(uint h) { return __uint_as_float(h << 16); }
__device__ __forceinline__ float bf_hi(uint h) { return __uint_as_float(h & 0xffff0000u); }

// mma.m16n8k16 bf16, fp32 accum
__device__ __forceinline__ void mma_bf16(float* c, const uint* a, uint b0, uint b1) {
    asm volatile("mma.sync.aligned.m16n8k16.row.col.f32.bf16.bf16.f32 "
        "{%0,%1,%2,%3}, {%4,%5,%6,%7}, {%8,%9}, {%0,%1,%2,%3};"
        : "+f"(c[0]), "+f"(c[1]), "+f"(c[2]), "+f"(c[3])
        : "r"(a[0]), "r"(a[1]), "r"(a[2]), "r"(a[3]), "r"(b0), "r"(b1));
}

// ---------------- setup: CC quadrature + Legendre tables (parallel fp64) ----------------
// grid 16 blocks x 128 threads; thread = (j_local 0..7, m 0..15)
__global__ void k_setup_leg() {
    __shared__ double sa[256], sb[256], sA1[17], sD[17];
    int t = threadIdx.x;
    const double PI = 3.14159265358979323846;
    if (t < 17) {
        sA1[t] = sqrt(2.0 * t + 1.0);
        sD[t]  = (t >= 1) ? sqrt((2.0 * t + 1.0) / (2.0 * t)) : 0.0;
    }
    if (t < 105) {
        int l = 2, acc = 0;
        while (acc + (l - 1) <= t) { acc += (l - 1); l++; }
        int m = t - acc;
        sa[m * 16 + l] = sqrt((2.0 * l - 1.0) / (l - m) * (2.0 * l + 1.0) / (l + m));
        sb[m * 16 + l] = sqrt((l + m - 1.0) / (l - m) * (2.0 * l + 1.0) / (2.0 * l - 3.0) *
                              (l - m - 1.0) / (l + m));
    }
    __syncthreads();

    int jl = t >> 4, m = t & 15;
    int j  = blockIdx.x * 8 + jl;

    double x = -cos(PI * (double)j / 127.0);
    float tj = (float)(PI * (double)j / 127.0);
    float w = 2.0f / 127.0f;
    #pragma unroll 4
    for (int kk = 1; kk <= 63; kk++)
        w -= 2.0f * cosf(2.0f * (float)kk * tj) * (2.0f / 127.0f) / (4.0f * kk * kk - 1.0f);
    if (j == 0 || j == 127) w *= 0.5f;

    double s = sqrt(fmax(0.0, (1.0 + x) * (1.0 - x)));
    double d = 1.0 / sqrt(4.0 * PI);
    for (int l = 1; l <= m; l++) d = sD[l] * s * d;     // diag[m]

    const double sc = 2.0 * PI / 256.0;
    double sgn = (m & 1) ? -1.0 : 1.0;
    double pa = d;
    g_wfwd[j * 256 + m * 16 + m]    = (float)(pa * sgn * w * sc);
    g_pct[(m * 16 + m) * NLAT + j]  = (float)(pa * sgn);
    if (m + 1 < 16) {
        double pb = sA1[m + 1] * x * pa;
        g_wfwd[j * 256 + (m + 1) * 16 + m]   = (float)(pb * sgn * w * sc);
        g_pct[(m * 16 + m + 1) * NLAT + j]   = (float)(pb * sgn);
        for (int l = m + 2; l < 16; l++) {
            double pc = sa[m * 16 + l] * x * pb - sb[m * 16 + l] * pa;
            pa = pb; pb = pc;
            g_wfwd[j * 256 + l * 16 + m]   = (float)(pc * sgn * w * sc);
            g_pct[(m * 16 + l) * NLAT + j] = (float)(pc * sgn);
        }
    }
}

__global__ void k_setup_tw() {
    int g = blockIdx.x * blockDim.x + threadIdx.x;   // 0..8191
    int isInv = (g >= NLON * M1D);
    int h = isInv ? g - NLON * M1D : g;
    int n = h >> 4, m = h & 15;
    int t = (m * n) & (NLON - 1);
    float fr = (float)t / 128.0f;                    // angle = pi * fr (exact fraction)
    float sn, cs;
    sincospif(fr, &sn, &cs);
    if (!isInv) {
        g_tw[h] = make_float2(cs, -sn);
    } else {
        float c = (m == 0) ? 1.0f : 2.0f * cs;
        float s = (m == 0) ? 0.0f : -2.0f * sn;
        g_itw[h] = make_float2(c, s);
    }
}

// ---------------- forward: 16-mode DFT + Legendre -> g_zh/g_zl ----------------
// thread = (k, m-half): 8 independent ffma2 chains, broadcast twiddle LDS.128.
__global__ void __launch_bounds__(256) k_forward(const float* __restrict__ x) {
    __shared__ __align__(16) char smraw[33280 + 8192];
    float* xs  = (float*)smraw;                 // [128][65]  (stage 1)
    ull*   Ys  = (ull*)smraw;                   // [128][16]  (overlay, stage 2)
    ull*   tws = (ull*)(smraw + 33280);         // [64][16]

    int bc  = blockIdx.x;
    int tid = threadIdx.x;
    int kk  = tid >> 1;             // 0..127 latitude row
    int mh  = (tid & 1) * 8;        // m base: 0 or 8
    const float* xb = x + (size_t)bc * NLAT * NLON;

    ull acc[8];
    #pragma unroll
    for (int j = 0; j < 8; j++) acc[j] = 0ull;

    for (int nc = 0; nc < 4; nc++) {
        #pragma unroll
        for (int i = 0; i < 32; i++) {
            int idx = i * 256 + tid;
            int k = idx >> 6, n = idx & 63;
            xs[k * 65 + n] = xb[k * 256 + nc * 64 + n];
        }
        #pragma unroll
        for (int i = 0; i < 4; i++) {
            int idx = i * 256 + tid;
            tws[idx] = ((const ull*)g_tw)[nc * 1024 + idx];
        }
        __syncthreads();
        #pragma unroll 4
        for (int n = 0; n < 64; n++) {
            float xv = xs[kk * 65 + n];
            ull xp = pack2(xv, xv);
            const ulonglong2* tp = (const ulonglong2*)&tws[n * 16 + mh];
            ulonglong2 t0 = tp[0], t1 = tp[1], t2 = tp[2], t3 = tp[3];
            acc[0] = ffma2(xp, t0.x, acc[0]);
            acc[1] = ffma2(xp, t0.y, acc[1]);
            acc[2] = ffma2(xp, t1.x, acc[2]);
            acc[3] = ffma2(xp, t1.y, acc[3]);
            acc[4] = ffma2(xp, t2.x, acc[4]);
            acc[5] = ffma2(xp, t2.y, acc[5]);
            acc[6] = ffma2(xp, t3.x, acc[6]);
            acc[7] = ffma2(xp, t3.y, acc[7]);
        }
        __syncthreads();
    }

    #pragma unroll
    for (int j = 0; j < 8; j++)
        Ys[kk * 16 + mh + j] = acc[j];
    __syncthreads();

    // stage 2: xh[l][m] = sum_k wfwd[k][l][m] * Y[k][m]
    int m = tid & 15;
    ull acc2 = 0ull;
    const float* wcol = g_wfwd + tid;
    #pragma unroll 8
    for (int k = 0; k < NLAT; k++) {
        float wv = wcol[k * 256];
        acc2 = ffma2(pack2(wv, wv), Ys[k * 16 + m], acc2);
    }
    float2 r = unpack2(acc2);
    int b = bc >> 3, c = bc & 7;
    int l = tid >> 4;
    size_t fo = (size_t)b * 4096 + c * 512 + l * 32 + m * 2;
    uint hz = cvtpack(r.x, r.y);
    uint lz = cvtpack(r.x - bf_lo(hz), r.y - bf_hi(hz));
    *(uint*)&g_zh[fo] = hz;
    *(uint*)&g_zl[fo] = lz;
}

// ---------------- bf16-split HMMA GEMM (single-sync double buffer) ----------------
// mode 0: Act=g_z*, P=g_p1, ldk=4096, Ntot=8192 (W=w0), grid (64,8)
// mode 1: Act=g_h*, P=g_p2, ldk=8192, Ntot=4096 (W=w1), grid (32,16)
// C[b=64][feat] partials over K-chunk 512. C = Ah*Wh + Al*Wh + Ah*Wl.
#define GEMM_SMEM_BYTES 61440

__global__ void __launch_bounds__(256) k_bgemm(int mode, const float* __restrict__ W)
{
    extern __shared__ __align__(16) __nv_bfloat16 sm[];
    __nv_bfloat16* WH = sm;            // 2 x 5120 halves (128 rows x 40)
    __nv_bfloat16* WL = sm + 10240;    // 2 x 5120
    __nv_bfloat16* AH = sm + 20480;    // 2 x 2560 (64 rows x 40)
    __nv_bfloat16* AL = sm + 25600;    // 2 x 2560

    const __nv_bfloat16* Ah_g; const __nv_bfloat16* Al_g;
    float* P; int ldk, Ntot;
    if (mode == 0) { Ah_g = g_zh; Al_g = g_zl; P = g_p1; ldk = 4096; Ntot = 8192; }
    else           { Ah_g = g_hh; Al_g = g_hl; P = g_p2; ldk = 8192; Ntot = 4096; }

    int tid = threadIdx.x, wid = tid >> 5, lane = tid & 31;
    int warpM = wid & 1;               // batch half (2 x 32 rows)
    int warpN = wid >> 1;              // feat 32-block (4)
    int g = lane >> 2, t = lane & 3;
    int tile = blockIdx.x;
    int kOff = blockIdx.y * 512;
    float* part = P + (size_t)blockIdx.y * 64 * Ntot;

    const float* Wt = W + (size_t)(tile * 128) * ldk + kOff;
    int aRow = tid >> 2;               // 0..63 activation row (batch)
    int aKg  = (tid & 3) * 8;          // 0,8,16,24

    float c[2][4][4];
    #pragma unroll
    for (int i = 0; i < 2; i++)
        #pragma unroll
        for (int jj = 0; jj < 4; jj++)
            #pragma unroll
            for (int q = 0; q < 4; q++) c[i][jj][q] = 0.f;

    float4 wv[4];
    uint4  avh, avl;
    // prefetch + store chunk 0 into buffer 0
    #pragma unroll
    for (int r = 0; r < 4; r++) {
        int idx = r * 256 + tid;
        wv[r] = *(const float4*)(Wt + (size_t)(idx >> 3) * ldk + ((idx & 7) * 4));
    }
    avh = *(const uint4*)(Ah_g + (size_t)aRow * ldk + kOff + aKg);
    avl = *(const uint4*)(Al_g + (size_t)aRow * ldk + kOff + aKg);
    {
        #pragma unroll
        for (int r = 0; r < 4; r++) {
            int idx = r * 256 + tid;
            int row = idx >> 3, kq = (idx & 7) * 4;
            uint h0 = cvtpack(wv[r].x, wv[r].y);
            uint h1 = cvtpack(wv[r].z, wv[r].w);
            uint l0 = cvtpack(wv[r].x - bf_lo(h0), wv[r].y - bf_hi(h0));
            uint l1 = cvtpack(wv[r].z - bf_lo(h1), wv[r].w - bf_hi(h1));
            *(uint2*)&WH[row * 40 + kq] = make_uint2(h0, h1);
            *(uint2*)&WL[row * 40 + kq] = make_uint2(l0, l1);
        }
        *(uint4*)&AH[aRow * 40 + aKg] = avh;
        *(uint4*)&AL[aRow * 40 + aKg] = avl;
    }
    __syncthreads();

    const int ITERS = 16;              // 16 * 32 = 512 K per split
    for (int it = 0; it < ITERS; it++) {
        if (it + 1 < ITERS) {
            int k0 = (it + 1) * 32;
            #pragma unroll
            for (int r = 0; r < 4; r++) {
                int idx = r * 256 + tid;
                wv[r] = *(const float4*)(Wt + (size_t)(idx >> 3) * ldk + k0 + ((idx & 7) * 4));
            }
            avh = *(const uint4*)(Ah_g + (size_t)aRow * ldk + kOff + k0 + aKg);
            avl = *(const uint4*)(Al_g + (size_t)aRow * ldk + kOff + k0 + aKg);
        }
        const __nv_bfloat16* cWH = WH + (it & 1) * 5120;
        const __nv_bfloat16* cWL = WL + (it & 1) * 5120;
        const __nv_bfloat16* cAH = AH + (it & 1) * 2560;
        const __nv_bfloat16* cAL = AL + (it & 1) * 2560;
        #pragma unroll
        for (int ks = 0; ks < 2; ks++) {
            int kb = ks * 16 + t * 2;
            uint ah[2][4], al[2][4];
            #pragma unroll
            for (int mi = 0; mi < 2; mi++) {
                int r0 = (warpM * 32 + mi * 16 + g) * 40 + kb;
                int r1 = r0 + 8 * 40;
                ah[mi][0] = *(const uint*)&cAH[r0];
                ah[mi][1] = *(const uint*)&cAH[r1];
                ah[mi][2] = *(const uint*)&cAH[r0 + 8];
                ah[mi][3] = *(const uint*)&cAH[r1 + 8];
                al[mi][0] = *(const uint*)&cAL[r0];
                al[mi][1] = *(const uint*)&cAL[r1];
                al[mi][2] = *(const uint*)&cAL[r0 + 8];
                al[mi][3] = *(const uint*)&cAL[r1 + 8];
            }
            uint wh[4][2], wl[4][2];
            #pragma unroll
            for (int nj = 0; nj < 4; nj++) {
                int o = (warpN * 32 + nj * 8 + g) * 40 + kb;
                wh[nj][0] = *(const uint*)&cWH[o];
                wh[nj][1] = *(const uint*)&cWH[o + 8];
                wl[nj][0] = *(const uint*)&cWL[o];
                wl[nj][1] = *(const uint*)&cWL[o + 8];
            }
            #pragma unroll
            for (int mi = 0; mi < 2; mi++)
                #pragma unroll
                for (int nj = 0; nj < 4; nj++) {
                    mma_bf16(c[mi][nj], ah[mi], wh[nj][0], wh[nj][1]);
                    mma_bf16(c[mi][nj], al[mi], wh[nj][0], wh[nj][1]);
                    mma_bf16(c[mi][nj], ah[mi], wl[nj][0], wl[nj][1]);
                }
        }
        if (it + 1 < ITERS) {
            // store next chunk into the OTHER buffer; safe: end-of-iter barrier below
            // guarantees everyone finished reading that buffer last iteration.
            int nb = (it + 1) & 1;
            __nv_bfloat16* nWH = WH + nb * 5120;
            __nv_bfloat16* nWL = WL + nb * 5120;
            __nv_bfloat16* nAH = AH + nb * 2560;
            __nv_bfloat16* nAL = AL + nb * 2560;
            #pragma unroll
            for (int r = 0; r < 4; r++) {
                int idx = r * 256 + tid;
                int row = idx >> 3, kq = (idx & 7) * 4;
                uint h0 = cvtpack(wv[r].x, wv[r].y);
                uint h1 = cvtpack(wv[r].z, wv[r].w);
                uint l0 = cvtpack(wv[r].x - bf_lo(h0), wv[r].y - bf_hi(h0));
                uint l1 = cvtpack(wv[r].z - bf_lo(h1), wv[r].w - bf_hi(h1));
                *(uint2*)&nWH[row * 40 + kq] = make_uint2(h0, h1);
                *(uint2*)&nWL[row * 40 + kq] = make_uint2(l0, l1);
            }
            *(uint4*)&nAH[aRow * 40 + aKg] = avh;
            *(uint4*)&nAL[aRow * 40 + aKg] = avl;
        }
        __syncthreads();
    }

    // C write: row = batch, col = global feature
    #pragma unroll
    for (int mi = 0; mi < 2; mi++) {
        #pragma unroll
        for (int nj = 0; nj < 4; nj++) {
            int row = warpM * 32 + mi * 16 + g;
            int col = tile * 128 + warpN * 32 + nj * 8 + t * 2;
            *(float2*)&part[(size_t)row * Ntot + col]       = make_float2(c[mi][nj][0], c[mi][nj][1]);
            *(float2*)&part[(size_t)(row + 8) * Ntot + col] = make_float2(c[mi][nj][2], c[mi][nj][3]);
        }
    }
}

// ---------------- epi1: reduce 8 partials + bias + gelu -> g_hh/g_hl (elementwise) ----------
__global__ void __launch_bounds__(256) k_epi1(const float* __restrict__ b0) {
    int i = blockIdx.x * 256 + threadIdx.x;          // float4 index over [64][8192] = 131072
    const float4* p = (const float4*)g_p1;
    float4 s0 = p[i];
    #pragma unroll
    for (int sk = 1; sk < 8; sk++) {
        float4 v = p[i + sk * 131072];
        s0.x += v.x; s0.y += v.y; s0.z += v.z; s0.w += v.w;
    }
    float4 bv = ((const float4*)b0)[i & 2047];       // feat4 = i mod 2048
    float f0 = gelu_exact(s0.x + bv.x);
    float f1 = gelu_exact(s0.y + bv.y);
    float f2 = gelu_exact(s0.z + bv.z);
    float f3 = gelu_exact(s0.w + bv.w);
    uint h0 = cvtpack(f0, f1), h1 = cvtpack(f2, f3);
    uint l0 = cvtpack(f0 - bf_lo(h0), f1 - bf_hi(h0));
    uint l1 = cvtpack(f2 - bf_lo(h1), f3 - bf_hi(h1));
    ((uint2*)g_hh)[i] = make_uint2(h0, h1);
    ((uint2*)g_hl)[i] = make_uint2(l0, l1);
}

// ---------------- epi2: reduce 16 partials -> g_ohf (elementwise) ----------------
__global__ void __launch_bounds__(256) k_epi2() {
    int i = blockIdx.x * 256 + threadIdx.x;          // float4 index over [64][4096] = 65536
    const float4* p = (const float4*)g_p2;
    float4 s = p[i];
    #pragma unroll
    for (int sK = 1; sK < 16; sK++) {
        float4 v = p[i + sK * 65536];
        s.x += v.x; s.y += v.y; s.z += v.z; s.w += v.w;
    }
    ((float4*)g_ohf)[i] = s;
}

// ---------------- inverse: Legendre + inverse DFT + bypass + gelu (validated) ----------
__global__ void __launch_bounds__(256) k_inverse(const float* __restrict__ x,
    const float* __restrict__ cw, const float* __restrict__ cb,
    float* __restrict__ out)
{
    __shared__ __align__(16) ull xks_u[8 * 32 * 16];
    __shared__ float cws[64];
    __shared__ float cbs[8];

    int tid = threadIdx.x;
    int b   = blockIdx.x >> 2;
    int kq  = blockIdx.x & 3;

    if (tid < 64) cws[tid] = cw[tid];
    if (tid < 8)  cbs[tid] = cb[tid];

    {
        int c  = tid >> 5;
        int kl = tid & 31;
        const float* p0 = g_ohf + (size_t)b * 4096 + c * 512;
        #pragma unroll 4
        for (int m = 0; m < 16; m++) {
            ull acc = 0ull;
            #pragma unroll
            for (int l = 0; l < 16; l++) {
                int off = l * 32 + m * 2;
                float pv = g_pct[(m * 16 + l) * NLAT + kq * 32 + kl];
                acc = ffma2(pack2(pv, pv), pack2(p0[off], p0[off + 1]), acc);
            }
            xks_u[(c * 32 + kl) * 16 + m] = acc;
        }
    }
    __syncthreads();

    int n = tid;
    ull itw_r[16];
    #pragma unroll
    for (int m = 0; m < 16; m++)
        itw_r[m] = ((const ull*)g_itw)[n * 16 + m];

    for (int kl = 0; kl < 32; kl++) {
        int k = kq * 32 + kl;
        float xv[8];
        #pragma unroll
        for (int c = 0; c < 8; c++)
            xv[c] = x[(((size_t)b * 8 + c) * NLAT + k) * NLON + n];
        #pragma unroll
        for (int o = 0; o < 8; o++) {
            const ulonglong2* xrow = (const ulonglong2*)&xks_u[(o * 32 + kl) * 16];
            ull acc = 0ull;
            #pragma unroll
            for (int mp = 0; mp < 8; mp++) {
                ulonglong2 xv2 = xrow[mp];
                acc = ffma2(xv2.x, itw_r[2 * mp],     acc);
                acc = ffma2(xv2.y, itw_r[2 * mp + 1], acc);
            }
            float2 ar = unpack2(acc);
            float spec = ar.x + ar.y;
            float byp = cbs[o];
            #pragma unroll
            for (int c = 0; c < 8; c++)
                byp = fmaf(xv[c], cws[o * 8 + c], byp);
            out[(((size_t)b * 8 + o) * NLAT + k) * NLON + n] = gelu_exact(spec + byp);
        }
    }
}

// ---------------- launch ----------------
extern "C" void kernel_launch(void* const* d_in, const int* in_sizes, int n_in,
                              void* d_out, int out_size) {
    const float* x  = (const float*)d_in[0];
    const float* w0 = (const float*)d_in[1];
    const float* b0 = (const float*)d_in[2];
    const float* w1 = (const float*)d_in[3];
    const float* cw = (const float*)d_in[4];
    const float* cb = (const float*)d_in[5];
    float* out = (float*)d_out;

    cudaFuncSetAttribute(k_bgemm, cudaFuncAttributeMaxDynamicSharedMemorySize, GEMM_SMEM_BYTES);

    k_setup_leg<<<16, 128>>>();
    k_setup_tw<<<32, 256>>>();
    k_forward<<<NB * CIN, 256>>>(x);
    // GEMM1: C[64][8192] = z[64][4096] @ w0[8192][4096]^T, splitK=8, 64 feat-tiles
    k_bgemm<<<dim3(64, 8), 256, GEMM_SMEM_BYTES>>>(0, w0);
    k_epi1<<<512, 256>>>(b0);
    // GEMM2: C[64][4096] = h[64][8192] @ w1[4096][8192]^T, splitK=16, 32 feat-tiles
    k_bgemm<<<dim3(32, 16), 256, GEMM_SMEM_BYTES>>>(1, w1);
    k_epi2<<<256, 256>>>();
    k_inverse<<<NB * 4, 256>>>(x, cw, cb, out);
}